// round 1
// baseline (speedup 1.0000x reference)
#include <cuda_runtime.h>
#include <cuda_bf16.h>

typedef unsigned long long ull;

#define M_TOT 16384   // B * L
#define L_SEQ 4096

// ---------------- scratch (static device globals: no allocation allowed) ----
__device__ float g_Xn[256 * M_TOT];     // layernormed x, (c, m) layout
__device__ float g_xz[1024 * M_TOT];    // in_proj out, (n, m); n<512 = xs_pre, n>=512 = z
__device__ float g_xs[512 * M_TOT];     // conv+silu activations, (d, m)
__device__ float g_xdbl[M_TOT * 48];    // x_proj out, (m, j): j<16 dt, 16..31 B, 32..47 C
__device__ float g_delta[512 * M_TOT];  // softplus(dt_proj), (d, m)
__device__ float g_y[512 * M_TOT];      // scan output after D-skip and z-gating, (d, m)
__device__ float g_Wc[512 * 128];       // mamba_out_w @ outp_w  (fused output weight)

// ---------------- f32x2 helpers --------------------------------------------
__device__ __forceinline__ ull pk2(float w) {
    unsigned u = __float_as_uint(w);
    ull r;
    asm("mov.b64 %0, {%1, %1};" : "=l"(r) : "r"(u));
    return r;
}
__device__ __forceinline__ ull fma2(ull a, ull b, ull c) {
    ull d;
    asm("fma.rn.f32x2 %0, %1, %2, %3;" : "=l"(d) : "l"(a), "l"(b), "l"(c));
    return d;
}
__device__ __forceinline__ float2 unpk(ull v) {
    unsigned lo, hi;
    asm("mov.b64 {%0, %1}, %2;" : "=r"(lo), "=r"(hi) : "l"(v));
    return make_float2(__uint_as_float(lo), __uint_as_float(hi));
}

// ---------------- K0: Wc = mamba_out_w (512x256) @ outp_w (256x128) ---------
__global__ void k_wc(const float* __restrict__ mw, const float* __restrict__ ow) {
    int d = blockIdx.x;      // 512
    int e = threadIdx.x;     // 128
    float acc = 0.f;
#pragma unroll 8
    for (int c = 0; c < 256; ++c)
        acc = fmaf(mw[d * 256 + c], ow[c * 128 + e], acc);
    g_Wc[d * 128 + e] = acc;
}

// ---------------- K1: fused concat + transpose + layernorm ------------------
// grid 128, block 128: thread handles one m column, loops 256 channels.
__global__ void k_ln(const float* __restrict__ in1, const float* __restrict__ in2,
                     const float* __restrict__ gg, const float* __restrict__ bb) {
    __shared__ float sg[256], sb[256];
    int tid = threadIdx.x;
    for (int c = tid; c < 256; c += 128) { sg[c] = gg[c]; sb[c] = bb[c]; }
    __syncthreads();

    int m = blockIdx.x * 128 + tid;
    int b = m >> 12, t = m & 4095;
    const float* p1 = in1 + (size_t)b * 128 * 4096 + t;
    const float* p2 = in2 + (size_t)b * 128 * 4096 + t;

    float s = 0.f, s2 = 0.f;
#pragma unroll 4
    for (int c = 0; c < 128; ++c) { float v = p1[c * 4096]; s += v; s2 += v * v; }
#pragma unroll 4
    for (int c = 0; c < 128; ++c) { float v = p2[c * 4096]; s += v; s2 += v * v; }
    float mu = s * (1.f / 256.f);
    float var = s2 * (1.f / 256.f) - mu * mu;
    float rs = rsqrtf(var + 1e-5f);
#pragma unroll 4
    for (int c = 0; c < 128; ++c) {
        float v = p1[c * 4096];
        g_Xn[(size_t)c * M_TOT + m] = (v - mu) * rs * sg[c] + sb[c];
    }
#pragma unroll 4
    for (int c = 0; c < 128; ++c) {
        float v = p2[c * 4096];
        g_Xn[(size_t)(128 + c) * M_TOT + m] = (v - mu) * rs * sg[128 + c] + sb[128 + c];
    }
}

// ---------------- K2: in_proj GEMM  xz(n,m) = W^T(1024x256) @ Xn(256,m) -----
// 128x128 tile, K-tile 16, f32x2 packed FMA. grid (128, 8), block 256.
__global__ void __launch_bounds__(256) k_inproj(const float* __restrict__ W) {
    __shared__ __align__(16) float Wsh[16][128];
    __shared__ __align__(16) float Xsh[16][128];
    int tid = threadIdx.x;
    int m0 = blockIdx.x * 128, n0 = blockIdx.y * 128;
    int tm = tid & 15, tn = tid >> 4;

    ull acc[8][4];
#pragma unroll
    for (int i = 0; i < 8; i++)
#pragma unroll
        for (int p = 0; p < 4; p++) acc[i][p] = 0ull;

    for (int k0 = 0; k0 < 256; k0 += 16) {
#pragma unroll
        for (int r = 0; r < 2; ++r) {
            int lin = r * 256 + tid;
            int row = lin >> 5, c4 = (lin & 31) << 2;
            *(float4*)&Wsh[row][c4] = *(const float4*)&W[(size_t)(k0 + row) * 1024 + n0 + c4];
            *(float4*)&Xsh[row][c4] = *(const float4*)&g_Xn[(size_t)(k0 + row) * M_TOT + m0 + c4];
        }
        __syncthreads();
#pragma unroll
        for (int kk = 0; kk < 16; ++kk) {
            float w[8];
            *(float4*)&w[0] = *(const float4*)&Wsh[kk][tn * 8];
            *(float4*)&w[4] = *(const float4*)&Wsh[kk][tn * 8 + 4];
            ulonglong2 xa = *(const ulonglong2*)&Xsh[kk][tm * 8];
            ulonglong2 xb = *(const ulonglong2*)&Xsh[kk][tm * 8 + 4];
            ull x0 = xa.x, x1 = xa.y, x2 = xb.x, x3 = xb.y;
#pragma unroll
            for (int i = 0; i < 8; i++) {
                ull wp = pk2(w[i]);
                acc[i][0] = fma2(wp, x0, acc[i][0]);
                acc[i][1] = fma2(wp, x1, acc[i][1]);
                acc[i][2] = fma2(wp, x2, acc[i][2]);
                acc[i][3] = fma2(wp, x3, acc[i][3]);
            }
        }
        __syncthreads();
    }
#pragma unroll
    for (int i = 0; i < 8; i++) {
        float o[8];
#pragma unroll
        for (int p = 0; p < 4; p++) {
            float2 u = unpk(acc[i][p]);
            o[2 * p] = u.x; o[2 * p + 1] = u.y;
        }
        float* dst = &g_xz[(size_t)(n0 + tn * 8 + i) * M_TOT + m0 + tm * 8];
        *(float4*)&dst[0] = *(float4*)&o[0];
        *(float4*)&dst[4] = *(float4*)&o[4];
    }
}

// ---------------- K3: causal depthwise conv(4) + bias + silu ----------------
// grid (64, 512), block 256.
__global__ void k_conv(const float* __restrict__ cw, const float* __restrict__ cb) {
    int d = blockIdx.y;
    int m = blockIdx.x * 256 + threadIdx.x;
    int t = m & 4095;
    const float* row = g_xz + (size_t)d * M_TOT;
    float w0 = cw[d * 4 + 0], w1 = cw[d * 4 + 1], w2 = cw[d * 4 + 2], w3 = cw[d * 4 + 3];
    float acc = cb[d];
    acc = fmaf(row[m], w3, acc);
    if (t >= 1) acc = fmaf(row[m - 1], w2, acc);
    if (t >= 2) acc = fmaf(row[m - 2], w1, acc);
    if (t >= 3) acc = fmaf(row[m - 3], w0, acc);
    acc = acc / (1.f + __expf(-acc));   // silu
    g_xs[(size_t)d * M_TOT + m] = acc;
}

// ---------------- K4: x_proj GEMM  x_dbl(m,48) = xs^T(m,512) @ xw(512,48) ---
// grid 128, block 256: micro 6j x 4m per thread.
__global__ void __launch_bounds__(256) k_xproj(const float* __restrict__ xw) {
    __shared__ __align__(16) float Ash[32][128];
    __shared__ float Wsh[32][48];
    int tid = threadIdx.x;
    int m0 = blockIdx.x * 128;
    int tj = tid >> 5, tm = tid & 31;
    float acc[6][4] = {};

    for (int k0 = 0; k0 < 512; k0 += 32) {
#pragma unroll
        for (int r = 0; r < 4; ++r) {
            int lin = r * 256 + tid;
            int row = lin >> 5, c4 = (lin & 31) << 2;
            *(float4*)&Ash[row][c4] = *(const float4*)&g_xs[(size_t)(k0 + row) * M_TOT + m0 + c4];
        }
#pragma unroll
        for (int r = 0; r < 6; ++r) {
            int lin = r * 256 + tid;   // 1536 total
            int row = lin / 48, col = lin % 48;
            Wsh[row][col] = xw[(k0 + row) * 48 + col];
        }
        __syncthreads();
#pragma unroll
        for (int kk = 0; kk < 32; ++kk) {
            float a[4];
            *(float4*)&a[0] = *(const float4*)&Ash[kk][tm * 4];
#pragma unroll
            for (int q = 0; q < 6; ++q) {
                float w = Wsh[kk][tj * 6 + q];
#pragma unroll
                for (int p = 0; p < 4; ++p) acc[q][p] = fmaf(w, a[p], acc[q][p]);
            }
        }
        __syncthreads();
    }
#pragma unroll
    for (int p = 0; p < 4; ++p) {
        int m = m0 + tm * 4 + p;
#pragma unroll
        for (int q = 0; q < 6; ++q)
            g_xdbl[(size_t)m * 48 + tj * 6 + q] = acc[q][p];
    }
}

// ---------------- K5: delta = softplus(dt @ dt_proj_w + b), (d,m) layout ----
// grid (64, 4): 256 m x 128 d per block.
__global__ void __launch_bounds__(256) k_dtproj(const float* __restrict__ dw,
                                                const float* __restrict__ db) {
    __shared__ float shw[16][128];
    __shared__ float shb[128];
    int tid = threadIdx.x;
    int m0 = blockIdx.x * 256;
    int d0 = blockIdx.y * 128;
#pragma unroll
    for (int r = 0; r < 8; ++r) {
        int lin = r * 256 + tid;       // 2048 = 16*128
        int row = lin >> 7, col = lin & 127;
        shw[row][col] = dw[row * 512 + d0 + col];
    }
    if (tid < 128) shb[tid] = db[d0 + tid];
    __syncthreads();

    float rr[16];
#pragma unroll
    for (int r = 0; r < 16; ++r) rr[r] = g_xdbl[(size_t)(m0 + tid) * 48 + r];

    for (int d = 0; d < 128; ++d) {
        float acc = shb[d];
#pragma unroll
        for (int r = 0; r < 16; ++r) acc = fmaf(rr[r], shw[r][d], acc);
        float sp = (acc > 20.f) ? acc : log1pf(__expf(acc));
        g_delta[(size_t)(d0 + d) * M_TOT + m0 + tid] = sp;
    }
}

// ---------------- K6: selective scan + D-skip + silu(z) gating --------------
// thread = (b, d, n); 16-lane groups reduce over n via shfl.xor.
// grid 128, block 256 (16 (b,d) pairs per block).
__global__ void __launch_bounds__(256) k_scan(const float* __restrict__ A_log,
                                              const float* __restrict__ Dp_) {
    int tid = threadIdx.x;
    int n = tid & 15;
    int pair = blockIdx.x * 16 + (tid >> 4);   // 0..2047 = b*512 + d
    int b = pair >> 9;
    int d = pair & 511;

    float Acoef = -__expf(A_log[d * 16 + n]);
    float Dv = Dp_[d];

    const float* pdelta = g_delta + (size_t)d * M_TOT + b * L_SEQ;
    const float* px     = g_xs    + (size_t)d * M_TOT + b * L_SEQ;
    const float* pz     = g_xz    + (size_t)(512 + d) * M_TOT + b * L_SEQ;
    const float* pB     = g_xdbl  + (size_t)b * L_SEQ * 48 + 16 + n;
    const float* pC     = pB + 16;
    float* py           = g_y     + (size_t)d * M_TOT + b * L_SEQ;

    float h = 0.f;
#pragma unroll 4
    for (int t = 0; t < L_SEQ; ++t) {
        float dl = pdelta[t];
        float xv = px[t];
        float Bv = pB[t * 48];
        float Cv = pC[t * 48];
        float dA = __expf(dl * Acoef);
        h = fmaf(h, dA, dl * xv * Bv);
        float p = h * Cv;
        p += __shfl_xor_sync(0xffffffffu, p, 8);
        p += __shfl_xor_sync(0xffffffffu, p, 4);
        p += __shfl_xor_sync(0xffffffffu, p, 2);
        p += __shfl_xor_sync(0xffffffffu, p, 1);
        if (n == 0) {
            float zv = pz[t];
            float yv = fmaf(xv, Dv, p);
            yv = yv * zv * (1.f / (1.f + __expf(-zv)));   // * silu(z)
            py[t] = yv;
        }
    }
}

// ---------------- K7: out = y^T @ Wc + outp_b, permuted store (b,c,t) -------
// grid 128, block 256, 128m x 128c tile, f32x2.
__global__ void __launch_bounds__(256) k_outgemm(const float* __restrict__ ob,
                                                 float* __restrict__ out) {
    __shared__ __align__(16) float Wsh[16][128];
    __shared__ __align__(16) float Ash[16][128];
    int tid = threadIdx.x;
    int m0 = blockIdx.x * 128;
    int tm = tid & 15, tn = tid >> 4;

    ull acc[8][4];
#pragma unroll
    for (int i = 0; i < 8; i++)
#pragma unroll
        for (int p = 0; p < 4; p++) acc[i][p] = 0ull;

    for (int k0 = 0; k0 < 512; k0 += 16) {
#pragma unroll
        for (int r = 0; r < 2; ++r) {
            int lin = r * 256 + tid;
            int row = lin >> 5, c4 = (lin & 31) << 2;
            *(float4*)&Wsh[row][c4] = *(const float4*)&g_Wc[(size_t)(k0 + row) * 128 + c4];
            *(float4*)&Ash[row][c4] = *(const float4*)&g_y[(size_t)(k0 + row) * M_TOT + m0 + c4];
        }
        __syncthreads();
#pragma unroll
        for (int kk = 0; kk < 16; ++kk) {
            float w[8];
            *(float4*)&w[0] = *(const float4*)&Wsh[kk][tn * 8];
            *(float4*)&w[4] = *(const float4*)&Wsh[kk][tn * 8 + 4];
            ulonglong2 xa = *(const ulonglong2*)&Ash[kk][tm * 8];
            ulonglong2 xb = *(const ulonglong2*)&Ash[kk][tm * 8 + 4];
            ull x0 = xa.x, x1 = xa.y, x2 = xb.x, x3 = xb.y;
#pragma unroll
            for (int i = 0; i < 8; i++) {
                ull wp = pk2(w[i]);
                acc[i][0] = fma2(wp, x0, acc[i][0]);
                acc[i][1] = fma2(wp, x1, acc[i][1]);
                acc[i][2] = fma2(wp, x2, acc[i][2]);
                acc[i][3] = fma2(wp, x3, acc[i][3]);
            }
        }
        __syncthreads();
    }

    int b = m0 >> 12;
    int t0 = (m0 & 4095) + tm * 8;
#pragma unroll
    for (int i = 0; i < 8; i++) {
        int c = tn * 8 + i;
        float bias = ob[c];
        float o[8];
#pragma unroll
        for (int p = 0; p < 4; p++) {
            float2 u = unpk(acc[i][p]);
            o[2 * p] = u.x + bias; o[2 * p + 1] = u.y + bias;
        }
        float* dst = out + ((size_t)(b * 128 + c) << 12) + t0;
        *(float4*)&dst[0] = *(float4*)&o[0];
        *(float4*)&dst[4] = *(float4*)&o[4];
    }
}

// ---------------- launch -----------------------------------------------------
extern "C" void kernel_launch(void* const* d_in, const int* in_sizes, int n_in,
                              void* d_out, int out_size) {
    const float* input  = (const float*)d_in[0];
    const float* input2 = (const float*)d_in[1];
    const float* ln_g   = (const float*)d_in[2];
    const float* ln_b   = (const float*)d_in[3];
    const float* outp_w = (const float*)d_in[4];
    const float* outp_b = (const float*)d_in[5];
    const float* inproj = (const float*)d_in[6];
    const float* conv_w = (const float*)d_in[7];
    const float* conv_b = (const float*)d_in[8];
    const float* xproj  = (const float*)d_in[9];
    const float* dtw    = (const float*)d_in[10];
    const float* dtb    = (const float*)d_in[11];
    const float* A_log  = (const float*)d_in[12];
    const float* Dp     = (const float*)d_in[13];
    const float* mow    = (const float*)d_in[14];
    float* out = (float*)d_out;

    k_wc<<<512, 128>>>(mow, outp_w);                  // fused output weight
    k_ln<<<128, 128>>>(input, input2, ln_g, ln_b);    // concat + LN
    k_inproj<<<dim3(128, 8), 256>>>(inproj);          // big GEMM
    k_conv<<<dim3(64, 512), 256>>>(conv_w, conv_b);   // causal dwconv + silu
    k_xproj<<<128, 256>>>(xproj);                     // dt/B/C projection
    k_dtproj<<<dim3(64, 4), 256>>>(dtw, dtb);         // delta = softplus(...)
    k_scan<<<128, 256>>>(A_log, Dp);                  // selective scan + gate
    k_outgemm<<<128, 256>>>(outp_b, out);             // fused out GEMM + store
}

// round 3
// speedup vs baseline: 1.0592x; 1.0592x over previous
#include <cuda_runtime.h>
#include <cuda_bf16.h>
#include <cstdint>

typedef unsigned long long ull;

#define M_TOT 16384   // B * L
#define L_SEQ 4096

// ---------------- scratch ----------------------------------------------------
__device__ float g_Xn[256 * M_TOT];     // layernormed x, (c, m)
__device__ float g_xz[1024 * M_TOT];    // in_proj out, (n, m); n>=512 = z
__device__ float g_xs[512 * M_TOT];     // conv+silu, (d, m)
__device__ float g_xdbl[M_TOT * 48];    // x_proj out, (m, j)
__device__ float g_delta[512 * M_TOT];  // softplus(dt_proj), (d, m)
__device__ float g_y[512 * M_TOT];      // scan out (gated), (d, m)
__device__ __nv_bfloat16 g_WtH[1024 * 256];  // in_proj_w^T hi, [n][k]
__device__ __nv_bfloat16 g_WtL[1024 * 256];  // in_proj_w^T lo
__device__ __nv_bfloat16 g_WcH[128 * 512];   // (mamba_out_w @ outp_w)^T hi, [c][d]
__device__ __nv_bfloat16 g_WcL[128 * 512];   // lo

// ---------------- helpers ----------------------------------------------------
__device__ __forceinline__ uint32_t smem_u32(const void* p) {
    uint32_t a;
    asm("{ .reg .u64 t; cvta.to.shared.u64 t, %1; cvt.u32.u64 %0, t; }" : "=r"(a) : "l"(p));
    return a;
}

__device__ __forceinline__ void ldsm4(uint32_t* r, uint32_t addr) {
    asm volatile("ldmatrix.sync.aligned.m8n8.x4.shared.b16 {%0,%1,%2,%3}, [%4];"
        : "=r"(r[0]), "=r"(r[1]), "=r"(r[2]), "=r"(r[3]) : "r"(addr));
}
__device__ __forceinline__ void ldsm4t(uint32_t* r, uint32_t addr) {
    asm volatile("ldmatrix.sync.aligned.m8n8.x4.trans.shared.b16 {%0,%1,%2,%3}, [%4];"
        : "=r"(r[0]), "=r"(r[1]), "=r"(r[2]), "=r"(r[3]) : "r"(addr));
}
__device__ __forceinline__ void mma_bf16(float* d, const uint32_t* a, const uint32_t* b) {
    asm volatile("mma.sync.aligned.m16n8k16.row.col.f32.bf16.bf16.f32 "
        "{%0,%1,%2,%3}, {%4,%5,%6,%7}, {%8,%9}, {%0,%1,%2,%3};"
        : "+f"(d[0]), "+f"(d[1]), "+f"(d[2]), "+f"(d[3])
        : "r"(a[0]), "r"(a[1]), "r"(a[2]), "r"(a[3]), "r"(b[0]), "r"(b[1]));
}

__device__ __forceinline__ uint32_t pack_bf2(__nv_bfloat16 a, __nv_bfloat16 b) {
    return ((uint32_t)__bfloat16_as_ushort(b) << 16) | __bfloat16_as_ushort(a);
}

// ---------------- K_wt: split-transpose in_proj_w (256x1024) -> [n][k] bf16 --
__global__ void k_wt(const float* __restrict__ W) {
    __shared__ float t[32][33];
    int n0 = blockIdx.x * 32, k0 = blockIdx.y * 32;
    int x = threadIdx.x, y0 = threadIdx.y;
    for (int yy = y0; yy < 32; yy += 8) t[yy][x] = W[(k0 + yy) * 1024 + n0 + x];
    __syncthreads();
    for (int yy = y0; yy < 32; yy += 8) {
        float v = t[x][yy];
        __nv_bfloat16 h = __float2bfloat16(v);
        __nv_bfloat16 l = __float2bfloat16(v - __bfloat162float(h));
        g_WtH[(size_t)(n0 + yy) * 256 + k0 + x] = h;
        g_WtL[(size_t)(n0 + yy) * 256 + k0 + x] = l;
    }
}

// ---------------- K_wc: Wc^T[c][d] = sum_k mow[d][k] * outp_w[k][c], split ---
__global__ void k_wc(const float* __restrict__ mw, const float* __restrict__ ow) {
    int d = blockIdx.x;      // 512
    int e = threadIdx.x;     // 128 (c)
    float acc = 0.f;
#pragma unroll 8
    for (int c = 0; c < 256; ++c)
        acc = fmaf(mw[d * 256 + c], ow[c * 128 + e], acc);
    __nv_bfloat16 h = __float2bfloat16(acc);
    __nv_bfloat16 l = __float2bfloat16(acc - __bfloat162float(h));
    g_WcH[(size_t)e * 512 + d] = h;
    g_WcL[(size_t)e * 512 + d] = l;
}

// ---------------- K1: fused concat + layernorm, output (c, m) ---------------
__global__ void k_ln(const float* __restrict__ in1, const float* __restrict__ in2,
                     const float* __restrict__ gg, const float* __restrict__ bb) {
    __shared__ float sg[256], sb[256];
    int tid = threadIdx.x;
    for (int c = tid; c < 256; c += 128) { sg[c] = gg[c]; sb[c] = bb[c]; }
    __syncthreads();

    int m = blockIdx.x * 128 + tid;
    int b = m >> 12, t = m & 4095;
    const float* p1 = in1 + (size_t)b * 128 * 4096 + t;
    const float* p2 = in2 + (size_t)b * 128 * 4096 + t;

    float s = 0.f, s2 = 0.f;
#pragma unroll 4
    for (int c = 0; c < 128; ++c) { float v = p1[c * 4096]; s += v; s2 += v * v; }
#pragma unroll 4
    for (int c = 0; c < 128; ++c) { float v = p2[c * 4096]; s += v; s2 += v * v; }
    float mu = s * (1.f / 256.f);
    float var = s2 * (1.f / 256.f) - mu * mu;
    float rs = rsqrtf(var + 1e-5f);
#pragma unroll 4
    for (int c = 0; c < 128; ++c) {
        float v = p1[c * 4096];
        g_Xn[(size_t)c * M_TOT + m] = (v - mu) * rs * sg[c] + sb[c];
    }
#pragma unroll 4
    for (int c = 0; c < 128; ++c) {
        float v = p2[c * 4096];
        g_Xn[(size_t)(128 + c) * M_TOT + m] = (v - mu) * rs * sg[128 + c] + sb[128 + c];
    }
}

// ---------------- warp-MMA GEMM (split bf16, 3 terms) ------------------------
// D[row=feature][col=m] = sum_k A[row][k] * B[k][col]
// A: precomputed bf16 hi/lo, [rows][KT] k-contiguous.
// B: f32 source in (k, m) layout (row stride M_TOT), converted on the fly.
// Block: 256 thr (8 warps, 2 row x 4 col), tile 128x128, k-chunk 64.
#define SA_H 0
#define SA_L 16384
#define SB_H 32768
#define SB_L 49152
#define SMEM_MMA 65536

template<int KT, bool IS_OUT>
__global__ void __launch_bounds__(256) k_mma(
    const __nv_bfloat16* __restrict__ AH, const __nv_bfloat16* __restrict__ AL,
    const float* __restrict__ Bsrc, float* __restrict__ outp,
    const float* __restrict__ bias)
{
    extern __shared__ __align__(16) char sm[];
    const int tid = threadIdx.x;
    const int lane = tid & 31, wid = tid >> 5;
    const int wr = wid & 1, wc = wid >> 1;     // 2 x 4 warps
    const int m0 = blockIdx.x * 128, n0 = blockIdx.y * 128;
    const uint32_t smb = smem_u32(sm);

    float acc[4][4][4];
#pragma unroll
    for (int i = 0; i < 4; ++i)
#pragma unroll
        for (int j = 0; j < 4; ++j)
#pragma unroll
            for (int p = 0; p < 4; ++p) acc[i][j][p] = 0.f;

    for (int kc = 0; kc < KT / 64; ++kc) {
        __syncthreads();
        // ---- stage A (bf16 hi/lo, swizzled [row][k] 128B rows) ----
#pragma unroll
        for (int it = 0; it < 4; ++it) {
            int lin = it * 256 + tid;       // 0..1023 16B chunks
            int row = lin >> 3;
            int seg = lin & 7;
            size_t gof = (size_t)(n0 + row) * KT + kc * 64 + seg * 8;
            uint4 vh = *(const uint4*)&AH[gof];
            uint4 vl = *(const uint4*)&AL[gof];
            uint32_t off = row * 128 + ((seg ^ (row & 7)) << 4);
            *(uint4*)(sm + SA_H + off) = vh;
            *(uint4*)(sm + SA_L + off) = vl;
        }
        // ---- stage B (f32 -> bf16 hi/lo, swizzled [k][m] 256B rows) ----
#pragma unroll
        for (int it = 0; it < 8; ++it) {
            int lin = it * 256 + tid;       // 0..2047 float4s
            int k = lin >> 5;
            int m4 = (lin & 31) << 2;
            float4 v = *(const float4*)&Bsrc[(size_t)(kc * 64 + k) * M_TOT + m0 + m4];
            __nv_bfloat16 h0 = __float2bfloat16(v.x), h1 = __float2bfloat16(v.y);
            __nv_bfloat16 h2 = __float2bfloat16(v.z), h3 = __float2bfloat16(v.w);
            __nv_bfloat16 l0 = __float2bfloat16(v.x - __bfloat162float(h0));
            __nv_bfloat16 l1 = __float2bfloat16(v.y - __bfloat162float(h1));
            __nv_bfloat16 l2 = __float2bfloat16(v.z - __bfloat162float(h2));
            __nv_bfloat16 l3 = __float2bfloat16(v.w - __bfloat162float(h3));
            uint2 ph = make_uint2(pack_bf2(h0, h1), pack_bf2(h2, h3));
            uint2 pl = make_uint2(pack_bf2(l0, l1), pack_bf2(l2, l3));
            uint32_t off = k * 256 + (((m4 >> 3) ^ (k & 7)) << 4) + ((m4 & 7) << 1);
            *(uint2*)(sm + SB_H + off) = ph;
            *(uint2*)(sm + SB_L + off) = pl;
        }
        __syncthreads();

        // ---- compute 4 k16 steps ----
#pragma unroll
        for (int ks = 0; ks < 4; ++ks) {
            uint32_t afh[4][4], afl[4][4];
            {
                int row = wr * 64 + (lane & 7) + ((lane >> 3) & 1) * 8;
                int seg = ks * 2 + (lane >> 4);
#pragma unroll
                for (int rt = 0; rt < 4; ++rt) {
                    int r = row + rt * 16;
                    uint32_t off = r * 128 + ((seg ^ (r & 7)) << 4);
                    ldsm4(afh[rt], smb + SA_H + off);
                    ldsm4(afl[rt], smb + SA_L + off);
                }
            }
            uint32_t bfh[4][2], bfl[4][2];
            {
                int k = ks * 16 + (lane & 7) + ((lane >> 3) & 1) * 8;
#pragma unroll
                for (int half = 0; half < 2; ++half) {
                    int mseg = wc * 4 + half * 2 + (lane >> 4);
                    uint32_t off = k * 256 + ((mseg ^ (k & 7)) << 4);
                    uint32_t r[4];
                    ldsm4t(r, smb + SB_H + off);
                    bfh[half * 2][0] = r[0]; bfh[half * 2][1] = r[1];
                    bfh[half * 2 + 1][0] = r[2]; bfh[half * 2 + 1][1] = r[3];
                    ldsm4t(r, smb + SB_L + off);
                    bfl[half * 2][0] = r[0]; bfl[half * 2][1] = r[1];
                    bfl[half * 2 + 1][0] = r[2]; bfl[half * 2 + 1][1] = r[3];
                }
            }
#pragma unroll
            for (int rt = 0; rt < 4; ++rt)
#pragma unroll
                for (int ct = 0; ct < 4; ++ct) {
                    mma_bf16(acc[rt][ct], afh[rt], bfh[ct]);
                    mma_bf16(acc[rt][ct], afh[rt], bfl[ct]);
                    mma_bf16(acc[rt][ct], afl[rt], bfh[ct]);
                }
        }
    }

    // ---- epilogue: direct float2 stores from fragments ----
#pragma unroll
    for (int rt = 0; rt < 4; ++rt) {
        int row0 = n0 + wr * 64 + rt * 16 + (lane >> 2);
        int row1 = row0 + 8;
        float b0 = 0.f, b1 = 0.f;
        if (IS_OUT) { b0 = bias[row0]; b1 = bias[row1]; }
#pragma unroll
        for (int ct = 0; ct < 4; ++ct) {
            int col = m0 + wc * 32 + ct * 8 + (lane & 3) * 2;
            float2 v0 = make_float2(acc[rt][ct][0] + b0, acc[rt][ct][1] + b0);
            float2 v1 = make_float2(acc[rt][ct][2] + b1, acc[rt][ct][3] + b1);
            if (IS_OUT) {
                int bb = col >> 12, t = col & 4095;
                *(float2*)&outp[((size_t)(bb * 128 + row0) << 12) + t] = v0;
                *(float2*)&outp[((size_t)(bb * 128 + row1) << 12) + t] = v1;
            } else {
                *(float2*)&outp[(size_t)row0 * M_TOT + col] = v0;
                *(float2*)&outp[(size_t)row1 * M_TOT + col] = v1;
            }
        }
    }
}

// ---------------- K3: causal depthwise conv(4) + bias + silu ----------------
__global__ void k_conv(const float* __restrict__ cw, const float* __restrict__ cb) {
    int d = blockIdx.y;
    int m = blockIdx.x * 256 + threadIdx.x;
    int t = m & 4095;
    const float* row = g_xz + (size_t)d * M_TOT;
    float w0 = cw[d * 4 + 0], w1 = cw[d * 4 + 1], w2 = cw[d * 4 + 2], w3 = cw[d * 4 + 3];
    float acc = cb[d];
    acc = fmaf(row[m], w3, acc);
    if (t >= 1) acc = fmaf(row[m - 1], w2, acc);
    if (t >= 2) acc = fmaf(row[m - 2], w1, acc);
    if (t >= 3) acc = fmaf(row[m - 3], w0, acc);
    acc = acc / (1.f + __expf(-acc));   // silu
    g_xs[(size_t)d * M_TOT + m] = acc;
}

// ---------------- K4: x_proj GEMM  x_dbl(m,48) = xs^T(m,512) @ xw(512,48) ---
__global__ void __launch_bounds__(256) k_xproj(const float* __restrict__ xw) {
    __shared__ __align__(16) float Ash[32][128];
    __shared__ float Wsh[32][48];
    int tid = threadIdx.x;
    int m0 = blockIdx.x * 128;
    int tj = tid >> 5, tm = tid & 31;
    float acc[6][4] = {};

    for (int k0 = 0; k0 < 512; k0 += 32) {
#pragma unroll
        for (int r = 0; r < 4; ++r) {
            int lin = r * 256 + tid;
            int row = lin >> 5, c4 = (lin & 31) << 2;
            *(float4*)&Ash[row][c4] = *(const float4*)&g_xs[(size_t)(k0 + row) * M_TOT + m0 + c4];
        }
#pragma unroll
        for (int r = 0; r < 6; ++r) {
            int lin = r * 256 + tid;
            int row = lin / 48, col = lin % 48;
            Wsh[row][col] = xw[(k0 + row) * 48 + col];
        }
        __syncthreads();
#pragma unroll
        for (int kk = 0; kk < 32; ++kk) {
            float a[4];
            *(float4*)&a[0] = *(const float4*)&Ash[kk][tm * 4];
#pragma unroll
            for (int q = 0; q < 6; ++q) {
                float w = Wsh[kk][tj * 6 + q];
#pragma unroll
                for (int p = 0; p < 4; ++p) acc[q][p] = fmaf(w, a[p], acc[q][p]);
            }
        }
        __syncthreads();
    }
#pragma unroll
    for (int p = 0; p < 4; ++p) {
        int m = m0 + tm * 4 + p;
#pragma unroll
        for (int q = 0; q < 6; ++q)
            g_xdbl[(size_t)m * 48 + tj * 6 + q] = acc[q][p];
    }
}

// ---------------- K5: delta = softplus(dt @ dt_proj_w + b), (d,m) -----------
__global__ void __launch_bounds__(256) k_dtproj(const float* __restrict__ dw,
                                                const float* __restrict__ db) {
    __shared__ float shw[16][128];
    __shared__ float shb[128];
    int tid = threadIdx.x;
    int m0 = blockIdx.x * 256;
    int d0 = blockIdx.y * 128;
#pragma unroll
    for (int r = 0; r < 8; ++r) {
        int lin = r * 256 + tid;
        int row = lin >> 7, col = lin & 127;
        shw[row][col] = dw[row * 512 + d0 + col];
    }
    if (tid < 128) shb[tid] = db[d0 + tid];
    __syncthreads();

    float rr[16];
#pragma unroll
    for (int r = 0; r < 16; ++r) rr[r] = g_xdbl[(size_t)(m0 + tid) * 48 + r];

    for (int d = 0; d < 128; ++d) {
        float acc = shb[d];
#pragma unroll
        for (int r = 0; r < 16; ++r) acc = fmaf(rr[r], shw[r][d], acc);
        float sp = (acc > 20.f) ? acc : log1pf(__expf(acc));
        g_delta[(size_t)(d0 + d) * M_TOT + m0 + tid] = sp;
    }
}

// ---------------- K6: selective scan + D-skip + silu(z) gating --------------
__global__ void __launch_bounds__(256) k_scan(const float* __restrict__ A_log,
                                              const float* __restrict__ Dp_) {
    int tid = threadIdx.x;
    int n = tid & 15;
    int pair = blockIdx.x * 16 + (tid >> 4);   // b*512 + d
    int b = pair >> 9;
    int d = pair & 511;

    float Acoef = -__expf(A_log[d * 16 + n]);
    float Dv = Dp_[d];

    const float* pdelta = g_delta + (size_t)d * M_TOT + b * L_SEQ;
    const float* px     = g_xs    + (size_t)d * M_TOT + b * L_SEQ;
    const float* pz     = g_xz    + (size_t)(512 + d) * M_TOT + b * L_SEQ;
    const float* pB     = g_xdbl  + (size_t)b * L_SEQ * 48 + 16 + n;
    const float* pC     = pB + 16;
    float* py           = g_y     + (size_t)d * M_TOT + b * L_SEQ;

    float h = 0.f;
#pragma unroll 4
    for (int t = 0; t < L_SEQ; ++t) {
        float dl = pdelta[t];
        float xv = px[t];
        float Bv = pB[t * 48];
        float Cv = pC[t * 48];
        float dA = __expf(dl * Acoef);
        h = fmaf(h, dA, dl * xv * Bv);
        float p = h * Cv;
        p += __shfl_xor_sync(0xffffffffu, p, 8);
        p += __shfl_xor_sync(0xffffffffu, p, 4);
        p += __shfl_xor_sync(0xffffffffu, p, 2);
        p += __shfl_xor_sync(0xffffffffu, p, 1);
        if (n == 0) {
            float zv = pz[t];
            float yv = fmaf(xv, Dv, p);
            yv = yv * zv * (1.f / (1.f + __expf(-zv)));
            py[t] = yv;
        }
    }
}

// ---------------- launch -----------------------------------------------------
extern "C" void kernel_launch(void* const* d_in, const int* in_sizes, int n_in,
                              void* d_out, int out_size) {
    const float* input  = (const float*)d_in[0];
    const float* input2 = (const float*)d_in[1];
    const float* ln_g   = (const float*)d_in[2];
    const float* ln_b   = (const float*)d_in[3];
    const float* outp_w = (const float*)d_in[4];
    const float* outp_b = (const float*)d_in[5];
    const float* inproj = (const float*)d_in[6];
    const float* conv_w = (const float*)d_in[7];
    const float* conv_b = (const float*)d_in[8];
    const float* xproj  = (const float*)d_in[9];
    const float* dtw    = (const float*)d_in[10];
    const float* dtb    = (const float*)d_in[11];
    const float* A_log  = (const float*)d_in[12];
    const float* Dp     = (const float*)d_in[13];
    const float* mow    = (const float*)d_in[14];
    float* out = (float*)d_out;

    // device-global pointers for GEMM kernels
    __nv_bfloat16 *wtH, *wtL, *wcH, *wcL;
    float *xn, *xz, *y;
    cudaGetSymbolAddress((void**)&wtH, g_WtH);
    cudaGetSymbolAddress((void**)&wtL, g_WtL);
    cudaGetSymbolAddress((void**)&wcH, g_WcH);
    cudaGetSymbolAddress((void**)&wcL, g_WcL);
    cudaGetSymbolAddress((void**)&xn, g_Xn);
    cudaGetSymbolAddress((void**)&xz, g_xz);
    cudaGetSymbolAddress((void**)&y, g_y);

    cudaFuncSetAttribute(k_mma<256, false>,
                         cudaFuncAttributeMaxDynamicSharedMemorySize, SMEM_MMA);
    cudaFuncSetAttribute(k_mma<512, true>,
                         cudaFuncAttributeMaxDynamicSharedMemorySize, SMEM_MMA);

    k_wt<<<dim3(32, 8), dim3(32, 8)>>>(inproj);        // weight split-transpose
    k_wc<<<512, 128>>>(mow, outp_w);                   // fused output weight^T
    k_ln<<<128, 128>>>(input, input2, ln_g, ln_b);     // concat + LN -> (c,m)
    k_mma<256, false><<<dim3(128, 8), 256, SMEM_MMA>>>(wtH, wtL, xn, xz, nullptr);
    k_conv<<<dim3(64, 512), 256>>>(conv_w, conv_b);    // dwconv + silu
    k_xproj<<<128, 256>>>(xproj);                      // dt/B/C projection
    k_dtproj<<<dim3(64, 4), 256>>>(dtw, dtb);          // delta = softplus
    k_scan<<<128, 256>>>(A_log, Dp);                   // scan + gate -> (d,m)
    k_mma<512, true><<<dim3(128, 1), 256, SMEM_MMA>>>(wcH, wcL, y, out, outp_b);
}

// round 4
// speedup vs baseline: 3.6911x; 3.4848x over previous
#include <cuda_runtime.h>
#include <cuda_bf16.h>
#include <cstdint>

typedef unsigned long long ull;

#define M_TOT 16384   // B * L
#define L_SEQ 4096
#define NCHUNK 64
#define CLEN 64       // L_SEQ / NCHUNK

// ---------------- scratch ----------------------------------------------------
__device__ float g_Xn[256 * M_TOT];     // layernormed x, (c, m)
__device__ float g_xz[1024 * M_TOT];    // in_proj out, (n, m); n>=512 = z
__device__ float g_xs[512 * M_TOT];     // conv+silu, (d, m)
__device__ float g_xdbl[M_TOT * 48];    // x_proj out, (m, j)
__device__ float g_delta[512 * M_TOT];  // softplus(dt_proj), (d, m)
__device__ float g_y[512 * M_TOT];      // scan out (gated), (d, m)
__device__ float g_P[NCHUNK * 2048 * 16];   // chunk a-product, [c][p][n]
__device__ float g_Lh[NCHUNK * 2048 * 16];  // chunk local scan, [c][p][n]
__device__ float g_H[NCHUNK * 2048 * 16];   // chunk start state, [c][p][n]
__device__ __nv_bfloat16 g_WtH[1024 * 256];  // in_proj_w^T hi, [n][k]
__device__ __nv_bfloat16 g_WtL[1024 * 256];  // in_proj_w^T lo
__device__ __nv_bfloat16 g_WcH[128 * 512];   // (mamba_out_w @ outp_w)^T hi, [c][d]
__device__ __nv_bfloat16 g_WcL[128 * 512];   // lo

// ---------------- helpers ----------------------------------------------------
__device__ __forceinline__ uint32_t smem_u32(const void* p) {
    uint32_t a;
    asm("{ .reg .u64 t; cvta.to.shared.u64 t, %1; cvt.u32.u64 %0, t; }" : "=r"(a) : "l"(p));
    return a;
}

__device__ __forceinline__ void ldsm4(uint32_t* r, uint32_t addr) {
    asm volatile("ldmatrix.sync.aligned.m8n8.x4.shared.b16 {%0,%1,%2,%3}, [%4];"
        : "=r"(r[0]), "=r"(r[1]), "=r"(r[2]), "=r"(r[3]) : "r"(addr));
}
__device__ __forceinline__ void ldsm4t(uint32_t* r, uint32_t addr) {
    asm volatile("ldmatrix.sync.aligned.m8n8.x4.trans.shared.b16 {%0,%1,%2,%3}, [%4];"
        : "=r"(r[0]), "=r"(r[1]), "=r"(r[2]), "=r"(r[3]) : "r"(addr));
}
__device__ __forceinline__ void mma_bf16(float* d, const uint32_t* a, const uint32_t* b) {
    asm volatile("mma.sync.aligned.m16n8k16.row.col.f32.bf16.bf16.f32 "
        "{%0,%1,%2,%3}, {%4,%5,%6,%7}, {%8,%9}, {%0,%1,%2,%3};"
        : "+f"(d[0]), "+f"(d[1]), "+f"(d[2]), "+f"(d[3])
        : "r"(a[0]), "r"(a[1]), "r"(a[2]), "r"(a[3]), "r"(b[0]), "r"(b[1]));
}

__device__ __forceinline__ uint32_t pack_bf2(__nv_bfloat16 a, __nv_bfloat16 b) {
    return ((uint32_t)__bfloat16_as_ushort(b) << 16) | __bfloat16_as_ushort(a);
}

// ---------------- K_wt: split-transpose in_proj_w (256x1024) -> [n][k] bf16 --
__global__ void k_wt(const float* __restrict__ W) {
    __shared__ float t[32][33];
    int n0 = blockIdx.x * 32, k0 = blockIdx.y * 32;
    int x = threadIdx.x, y0 = threadIdx.y;
    for (int yy = y0; yy < 32; yy += 8) t[yy][x] = W[(k0 + yy) * 1024 + n0 + x];
    __syncthreads();
    for (int yy = y0; yy < 32; yy += 8) {
        float v = t[x][yy];
        __nv_bfloat16 h = __float2bfloat16(v);
        __nv_bfloat16 l = __float2bfloat16(v - __bfloat162float(h));
        g_WtH[(size_t)(n0 + yy) * 256 + k0 + x] = h;
        g_WtL[(size_t)(n0 + yy) * 256 + k0 + x] = l;
    }
}

// ---------------- K_wc: Wc^T[c][d] = sum_k mow[d][k] * outp_w[k][c], split ---
__global__ void k_wc(const float* __restrict__ mw, const float* __restrict__ ow) {
    int d = blockIdx.x;      // 512
    int e = threadIdx.x;     // 128 (c)
    float acc = 0.f;
#pragma unroll 8
    for (int c = 0; c < 256; ++c)
        acc = fmaf(mw[d * 256 + c], ow[c * 128 + e], acc);
    __nv_bfloat16 h = __float2bfloat16(acc);
    __nv_bfloat16 l = __float2bfloat16(acc - __bfloat162float(h));
    g_WcH[(size_t)e * 512 + d] = h;
    g_WcL[(size_t)e * 512 + d] = l;
}

// ---------------- K1: fused concat + layernorm, output (c, m) ---------------
__global__ void k_ln(const float* __restrict__ in1, const float* __restrict__ in2,
                     const float* __restrict__ gg, const float* __restrict__ bb) {
    __shared__ float sg[256], sb[256];
    int tid = threadIdx.x;
    for (int c = tid; c < 256; c += 128) { sg[c] = gg[c]; sb[c] = bb[c]; }
    __syncthreads();

    int m = blockIdx.x * 128 + tid;
    int b = m >> 12, t = m & 4095;
    const float* p1 = in1 + (size_t)b * 128 * 4096 + t;
    const float* p2 = in2 + (size_t)b * 128 * 4096 + t;

    float s = 0.f, s2 = 0.f;
#pragma unroll 4
    for (int c = 0; c < 128; ++c) { float v = p1[c * 4096]; s += v; s2 += v * v; }
#pragma unroll 4
    for (int c = 0; c < 128; ++c) { float v = p2[c * 4096]; s += v; s2 += v * v; }
    float mu = s * (1.f / 256.f);
    float var = s2 * (1.f / 256.f) - mu * mu;
    float rs = rsqrtf(var + 1e-5f);
#pragma unroll 4
    for (int c = 0; c < 128; ++c) {
        float v = p1[c * 4096];
        g_Xn[(size_t)c * M_TOT + m] = (v - mu) * rs * sg[c] + sb[c];
    }
#pragma unroll 4
    for (int c = 0; c < 128; ++c) {
        float v = p2[c * 4096];
        g_Xn[(size_t)(128 + c) * M_TOT + m] = (v - mu) * rs * sg[128 + c] + sb[128 + c];
    }
}

// ---------------- warp-MMA GEMM (split bf16, 3 terms) ------------------------
#define SA_H 0
#define SA_L 16384
#define SB_H 32768
#define SB_L 49152
#define SMEM_MMA 65536

template<int KT, bool IS_OUT>
__global__ void __launch_bounds__(256) k_mma(
    const __nv_bfloat16* __restrict__ AH, const __nv_bfloat16* __restrict__ AL,
    const float* __restrict__ Bsrc, float* __restrict__ outp,
    const float* __restrict__ bias)
{
    extern __shared__ __align__(16) char sm[];
    const int tid = threadIdx.x;
    const int lane = tid & 31, wid = tid >> 5;
    const int wr = wid & 1, wc = wid >> 1;     // 2 x 4 warps
    const int m0 = blockIdx.x * 128, n0 = blockIdx.y * 128;
    const uint32_t smb = smem_u32(sm);

    float acc[4][4][4];
#pragma unroll
    for (int i = 0; i < 4; ++i)
#pragma unroll
        for (int j = 0; j < 4; ++j)
#pragma unroll
            for (int p = 0; p < 4; ++p) acc[i][j][p] = 0.f;

    for (int kc = 0; kc < KT / 64; ++kc) {
        __syncthreads();
#pragma unroll
        for (int it = 0; it < 4; ++it) {
            int lin = it * 256 + tid;
            int row = lin >> 3;
            int seg = lin & 7;
            size_t gof = (size_t)(n0 + row) * KT + kc * 64 + seg * 8;
            uint4 vh = *(const uint4*)&AH[gof];
            uint4 vl = *(const uint4*)&AL[gof];
            uint32_t off = row * 128 + ((seg ^ (row & 7)) << 4);
            *(uint4*)(sm + SA_H + off) = vh;
            *(uint4*)(sm + SA_L + off) = vl;
        }
#pragma unroll
        for (int it = 0; it < 8; ++it) {
            int lin = it * 256 + tid;
            int k = lin >> 5;
            int m4 = (lin & 31) << 2;
            float4 v = *(const float4*)&Bsrc[(size_t)(kc * 64 + k) * M_TOT + m0 + m4];
            __nv_bfloat16 h0 = __float2bfloat16(v.x), h1 = __float2bfloat16(v.y);
            __nv_bfloat16 h2 = __float2bfloat16(v.z), h3 = __float2bfloat16(v.w);
            __nv_bfloat16 l0 = __float2bfloat16(v.x - __bfloat162float(h0));
            __nv_bfloat16 l1 = __float2bfloat16(v.y - __bfloat162float(h1));
            __nv_bfloat16 l2 = __float2bfloat16(v.z - __bfloat162float(h2));
            __nv_bfloat16 l3 = __float2bfloat16(v.w - __bfloat162float(h3));
            uint2 ph = make_uint2(pack_bf2(h0, h1), pack_bf2(h2, h3));
            uint2 pl = make_uint2(pack_bf2(l0, l1), pack_bf2(l2, l3));
            uint32_t off = k * 256 + (((m4 >> 3) ^ (k & 7)) << 4) + ((m4 & 7) << 1);
            *(uint2*)(sm + SB_H + off) = ph;
            *(uint2*)(sm + SB_L + off) = pl;
        }
        __syncthreads();

#pragma unroll
        for (int ks = 0; ks < 4; ++ks) {
            uint32_t afh[4][4], afl[4][4];
            {
                int row = wr * 64 + (lane & 7) + ((lane >> 3) & 1) * 8;
                int seg = ks * 2 + (lane >> 4);
#pragma unroll
                for (int rt = 0; rt < 4; ++rt) {
                    int r = row + rt * 16;
                    uint32_t off = r * 128 + ((seg ^ (r & 7)) << 4);
                    ldsm4(afh[rt], smb + SA_H + off);
                    ldsm4(afl[rt], smb + SA_L + off);
                }
            }
            uint32_t bfh[4][2], bfl[4][2];
            {
                int k = ks * 16 + (lane & 7) + ((lane >> 3) & 1) * 8;
#pragma unroll
                for (int half = 0; half < 2; ++half) {
                    int mseg = wc * 4 + half * 2 + (lane >> 4);
                    uint32_t off = k * 256 + ((mseg ^ (k & 7)) << 4);
                    uint32_t r[4];
                    ldsm4t(r, smb + SB_H + off);
                    bfh[half * 2][0] = r[0]; bfh[half * 2][1] = r[1];
                    bfh[half * 2 + 1][0] = r[2]; bfh[half * 2 + 1][1] = r[3];
                    ldsm4t(r, smb + SB_L + off);
                    bfl[half * 2][0] = r[0]; bfl[half * 2][1] = r[1];
                    bfl[half * 2 + 1][0] = r[2]; bfl[half * 2 + 1][1] = r[3];
                }
            }
#pragma unroll
            for (int rt = 0; rt < 4; ++rt)
#pragma unroll
                for (int ct = 0; ct < 4; ++ct) {
                    mma_bf16(acc[rt][ct], afh[rt], bfh[ct]);
                    mma_bf16(acc[rt][ct], afh[rt], bfl[ct]);
                    mma_bf16(acc[rt][ct], afl[rt], bfh[ct]);
                }
        }
    }

#pragma unroll
    for (int rt = 0; rt < 4; ++rt) {
        int row0 = n0 + wr * 64 + rt * 16 + (lane >> 2);
        int row1 = row0 + 8;
        float b0 = 0.f, b1 = 0.f;
        if (IS_OUT) { b0 = bias[row0]; b1 = bias[row1]; }
#pragma unroll
        for (int ct = 0; ct < 4; ++ct) {
            int col = m0 + wc * 32 + ct * 8 + (lane & 3) * 2;
            float2 v0 = make_float2(acc[rt][ct][0] + b0, acc[rt][ct][1] + b0);
            float2 v1 = make_float2(acc[rt][ct][2] + b1, acc[rt][ct][3] + b1);
            if (IS_OUT) {
                int bb = col >> 12, t = col & 4095;
                *(float2*)&outp[((size_t)(bb * 128 + row0) << 12) + t] = v0;
                *(float2*)&outp[((size_t)(bb * 128 + row1) << 12) + t] = v1;
            } else {
                *(float2*)&outp[(size_t)row0 * M_TOT + col] = v0;
                *(float2*)&outp[(size_t)row1 * M_TOT + col] = v1;
            }
        }
    }
}

// ---------------- K3: causal depthwise conv(4) + bias + silu ----------------
__global__ void k_conv(const float* __restrict__ cw, const float* __restrict__ cb) {
    int d = blockIdx.y;
    int m = blockIdx.x * 256 + threadIdx.x;
    int t = m & 4095;
    const float* row = g_xz + (size_t)d * M_TOT;
    float w0 = cw[d * 4 + 0], w1 = cw[d * 4 + 1], w2 = cw[d * 4 + 2], w3 = cw[d * 4 + 3];
    float acc = cb[d];
    acc = fmaf(row[m], w3, acc);
    if (t >= 1) acc = fmaf(row[m - 1], w2, acc);
    if (t >= 2) acc = fmaf(row[m - 2], w1, acc);
    if (t >= 3) acc = fmaf(row[m - 3], w0, acc);
    acc = acc / (1.f + __expf(-acc));   // silu
    g_xs[(size_t)d * M_TOT + m] = acc;
}

// ---------------- K4: x_proj GEMM  x_dbl(m,48) = xs^T(m,512) @ xw(512,48) ---
__global__ void __launch_bounds__(256) k_xproj(const float* __restrict__ xw) {
    __shared__ __align__(16) float Ash[32][128];
    __shared__ float Wsh[32][48];
    int tid = threadIdx.x;
    int m0 = blockIdx.x * 128;
    int tj = tid >> 5, tm = tid & 31;
    float acc[6][4] = {};

    for (int k0 = 0; k0 < 512; k0 += 32) {
#pragma unroll
        for (int r = 0; r < 4; ++r) {
            int lin = r * 256 + tid;
            int row = lin >> 5, c4 = (lin & 31) << 2;
            *(float4*)&Ash[row][c4] = *(const float4*)&g_xs[(size_t)(k0 + row) * M_TOT + m0 + c4];
        }
#pragma unroll
        for (int r = 0; r < 6; ++r) {
            int lin = r * 256 + tid;
            int row = lin / 48, col = lin % 48;
            Wsh[row][col] = xw[(k0 + row) * 48 + col];
        }
        __syncthreads();
#pragma unroll
        for (int kk = 0; kk < 32; ++kk) {
            float a[4];
            *(float4*)&a[0] = *(const float4*)&Ash[kk][tm * 4];
#pragma unroll
            for (int q = 0; q < 6; ++q) {
                float w = Wsh[kk][tj * 6 + q];
#pragma unroll
                for (int p = 0; p < 4; ++p) acc[q][p] = fmaf(w, a[p], acc[q][p]);
            }
        }
        __syncthreads();
    }
#pragma unroll
    for (int p = 0; p < 4; ++p) {
        int m = m0 + tm * 4 + p;
#pragma unroll
        for (int q = 0; q < 6; ++q)
            g_xdbl[(size_t)m * 48 + tj * 6 + q] = acc[q][p];
    }
}

// ---------------- K5: delta = softplus(dt @ dt_proj_w + b), (d,m) -----------
__global__ void __launch_bounds__(256) k_dtproj(const float* __restrict__ dw,
                                                const float* __restrict__ db) {
    __shared__ float shw[16][128];
    __shared__ float shb[128];
    int tid = threadIdx.x;
    int m0 = blockIdx.x * 256;
    int d0 = blockIdx.y * 128;
#pragma unroll
    for (int r = 0; r < 8; ++r) {
        int lin = r * 256 + tid;
        int row = lin >> 7, col = lin & 127;
        shw[row][col] = dw[row * 512 + d0 + col];
    }
    if (tid < 128) shb[tid] = db[d0 + tid];
    __syncthreads();

    float rr[16];
#pragma unroll
    for (int r = 0; r < 16; ++r) rr[r] = g_xdbl[(size_t)(m0 + tid) * 48 + r];

    for (int d = 0; d < 128; ++d) {
        float acc = shb[d];
#pragma unroll
        for (int r = 0; r < 16; ++r) acc = fmaf(rr[r], shw[r][d], acc);
        float sp = (acc > 20.f) ? acc : log1pf(__expf(acc));
        g_delta[(size_t)(d0 + d) * M_TOT + m0 + tid] = sp;
    }
}

// ---------------- chunked selective scan -------------------------------------
// Phase A: per (p, n, chunk): P = prod a_t, Lh = local scan (h0 = 0).
// Block 256 = 16 groups x 16 lanes; grid (128 p-groups, 64 chunks).
__global__ void __launch_bounds__(256) k_scanA(const float* __restrict__ A_log) {
    int tid = threadIdx.x;
    int n = tid & 15;
    int p = blockIdx.x * 16 + (tid >> 4);      // b*512 + d
    int b = p >> 9, d = p & 511;
    int c = blockIdx.y;
    int t0 = c * CLEN;

    float Acoef = -__expf(A_log[d * 16 + n]);
    const float* pdelta = g_delta + (size_t)d * M_TOT + b * L_SEQ + t0;
    const float* px     = g_xs    + (size_t)d * M_TOT + b * L_SEQ + t0;
    const float* pB     = g_xdbl  + (size_t)(b * L_SEQ + t0) * 48 + 16 + n;

    float h = 0.f, P = 1.f;
#pragma unroll 4
    for (int t = 0; t < CLEN; ++t) {
        float dl = pdelta[t];
        float xv = px[t];
        float Bv = pB[t * 48];
        float a = __expf(dl * Acoef);
        h = fmaf(h, a, dl * xv * Bv);
        P *= a;
    }
    int idx = c * 32768 + p * 16 + n;
    g_P[idx] = P;
    g_Lh[idx] = h;
}

// Phase B: scan across chunks. thread = (p, n). [c][p][n] layout: coalesced.
__global__ void __launch_bounds__(256) k_scanB() {
    int gid = blockIdx.x * 256 + threadIdx.x;   // 0..32767
    float h = 0.f;
#pragma unroll 8
    for (int c = 0; c < NCHUNK; ++c) {
        int idx = c * 32768 + gid;
        g_H[idx] = h;                 // state at chunk start
        h = fmaf(h, g_P[idx], g_Lh[idx]);
    }
}

// Phase C: recompute within chunk from h_start, reduce over n, gate, store y.
__global__ void __launch_bounds__(256) k_scanC(const float* __restrict__ A_log,
                                               const float* __restrict__ Dp_) {
    int tid = threadIdx.x;
    int n = tid & 15;
    int p = blockIdx.x * 16 + (tid >> 4);
    int b = p >> 9, d = p & 511;
    int c = blockIdx.y;
    int t0 = c * CLEN;

    float Acoef = -__expf(A_log[d * 16 + n]);
    float Dv = Dp_[d];
    const float* pdelta = g_delta + (size_t)d * M_TOT + b * L_SEQ + t0;
    const float* px     = g_xs    + (size_t)d * M_TOT + b * L_SEQ + t0;
    const float* pz     = g_xz    + (size_t)(512 + d) * M_TOT + b * L_SEQ + t0;
    const float* pB     = g_xdbl  + (size_t)(b * L_SEQ + t0) * 48 + 16 + n;
    const float* pC     = pB + 16;
    float* py           = g_y     + (size_t)d * M_TOT + b * L_SEQ + t0;

    float h = g_H[c * 32768 + p * 16 + n];
#pragma unroll 4
    for (int t = 0; t < CLEN; ++t) {
        float dl = pdelta[t];
        float xv = px[t];
        float Bv = pB[t * 48];
        float Cv = pC[t * 48];
        float a = __expf(dl * Acoef);
        h = fmaf(h, a, dl * xv * Bv);
        float pr = h * Cv;
        pr += __shfl_xor_sync(0xffffffffu, pr, 8);
        pr += __shfl_xor_sync(0xffffffffu, pr, 4);
        pr += __shfl_xor_sync(0xffffffffu, pr, 2);
        pr += __shfl_xor_sync(0xffffffffu, pr, 1);
        if (n == 0) {
            float zv = pz[t];
            float yv = fmaf(xv, Dv, pr);
            yv = yv * zv * (1.f / (1.f + __expf(-zv)));
            py[t] = yv;
        }
    }
}

// ---------------- launch -----------------------------------------------------
extern "C" void kernel_launch(void* const* d_in, const int* in_sizes, int n_in,
                              void* d_out, int out_size) {
    const float* input  = (const float*)d_in[0];
    const float* input2 = (const float*)d_in[1];
    const float* ln_g   = (const float*)d_in[2];
    const float* ln_b   = (const float*)d_in[3];
    const float* outp_w = (const float*)d_in[4];
    const float* outp_b = (const float*)d_in[5];
    const float* inproj = (const float*)d_in[6];
    const float* conv_w = (const float*)d_in[7];
    const float* conv_b = (const float*)d_in[8];
    const float* xproj  = (const float*)d_in[9];
    const float* dtw    = (const float*)d_in[10];
    const float* dtb    = (const float*)d_in[11];
    const float* A_log  = (const float*)d_in[12];
    const float* Dp     = (const float*)d_in[13];
    const float* mow    = (const float*)d_in[14];
    float* out = (float*)d_out;

    __nv_bfloat16 *wtH, *wtL, *wcH, *wcL;
    float *xn, *xz, *y;
    cudaGetSymbolAddress((void**)&wtH, g_WtH);
    cudaGetSymbolAddress((void**)&wtL, g_WtL);
    cudaGetSymbolAddress((void**)&wcH, g_WcH);
    cudaGetSymbolAddress((void**)&wcL, g_WcL);
    cudaGetSymbolAddress((void**)&xn, g_Xn);
    cudaGetSymbolAddress((void**)&xz, g_xz);
    cudaGetSymbolAddress((void**)&y, g_y);

    cudaFuncSetAttribute(k_mma<256, false>,
                         cudaFuncAttributeMaxDynamicSharedMemorySize, SMEM_MMA);
    cudaFuncSetAttribute(k_mma<512, true>,
                         cudaFuncAttributeMaxDynamicSharedMemorySize, SMEM_MMA);

    k_wt<<<dim3(32, 8), dim3(32, 8)>>>(inproj);        // weight split-transpose
    k_wc<<<512, 128>>>(mow, outp_w);                   // fused output weight^T
    k_ln<<<128, 128>>>(input, input2, ln_g, ln_b);     // concat + LN -> (c,m)
    k_mma<256, false><<<dim3(128, 8), 256, SMEM_MMA>>>(wtH, wtL, xn, xz, nullptr);
    k_conv<<<dim3(64, 512), 256>>>(conv_w, conv_b);    // dwconv + silu
    k_xproj<<<128, 256>>>(xproj);                      // dt/B/C projection
    k_dtproj<<<dim3(64, 4), 256>>>(dtw, dtb);          // delta = softplus
    k_scanA<<<dim3(128, 64), 256>>>(A_log);            // chunk local scans
    k_scanB<<<128, 256>>>();                           // cross-chunk scan
    k_scanC<<<dim3(128, 64), 256>>>(A_log, Dp);        // recompute + gate
    k_mma<512, true><<<dim3(128, 1), 256, SMEM_MMA>>>(wcH, wcL, y, out, outp_b);
}

// round 5
// speedup vs baseline: 4.7839x; 1.2961x over previous
#include <cuda_runtime.h>
#include <cuda_bf16.h>
#include <cstdint>

typedef unsigned long long ull;

#define M_TOT 16384   // B * L
#define L_SEQ 4096
#define NCHUNK 64
#define CLEN 64       // L_SEQ / NCHUNK

// ---------------- scratch ----------------------------------------------------
__device__ __align__(16) float g_xz[1024 * M_TOT];    // in_proj out (n,m); n>=512 = z
__device__ __align__(16) float g_xs[512 * M_TOT];     // conv+silu, (d, m)
__device__ __align__(16) float g_xdbl[M_TOT * 48];    // x_proj out, (m, j) [j>=16 used]
__device__ __align__(16) float g_delta[512 * M_TOT];  // softplus(dt_proj), (d, m)
__device__ __align__(16) float g_P[NCHUNK * 2048 * 16];   // chunk a-prod, [c][p][n]
__device__ __align__(16) float g_Lh[NCHUNK * 2048 * 16];  // chunk local scan
__device__ __align__(16) float g_H[NCHUNK * 2048 * 16];   // chunk start state
__device__ __align__(16) __nv_bfloat16 g_XnH[256 * M_TOT];  // LN out hi, (c,m)
__device__ __align__(16) __nv_bfloat16 g_XnL[256 * M_TOT];  // LN out lo
__device__ __align__(16) __nv_bfloat16 g_yH[512 * M_TOT];   // scan out hi, (d,m)
__device__ __align__(16) __nv_bfloat16 g_yL[512 * M_TOT];   // scan out lo
__device__ __align__(16) __nv_bfloat16 g_WtH[1024 * 256];   // in_proj_w^T hi, [n][k]
__device__ __align__(16) __nv_bfloat16 g_WtL[1024 * 256];
__device__ __align__(16) __nv_bfloat16 g_WcH[128 * 512];    // (mow@outp_w)^T hi, [c][d]
__device__ __align__(16) __nv_bfloat16 g_WcL[128 * 512];

// ---------------- helpers ----------------------------------------------------
__device__ __forceinline__ uint32_t smem_u32(const void* p) {
    uint32_t a;
    asm("{ .reg .u64 t; cvta.to.shared.u64 t, %1; cvt.u32.u64 %0, t; }" : "=r"(a) : "l"(p));
    return a;
}
__device__ __forceinline__ void ldsm4(uint32_t* r, uint32_t addr) {
    asm volatile("ldmatrix.sync.aligned.m8n8.x4.shared.b16 {%0,%1,%2,%3}, [%4];"
        : "=r"(r[0]), "=r"(r[1]), "=r"(r[2]), "=r"(r[3]) : "r"(addr));
}
__device__ __forceinline__ void ldsm4t(uint32_t* r, uint32_t addr) {
    asm volatile("ldmatrix.sync.aligned.m8n8.x4.trans.shared.b16 {%0,%1,%2,%3}, [%4];"
        : "=r"(r[0]), "=r"(r[1]), "=r"(r[2]), "=r"(r[3]) : "r"(addr));
}
__device__ __forceinline__ void mma_bf16(float* d, const uint32_t* a, const uint32_t* b) {
    asm volatile("mma.sync.aligned.m16n8k16.row.col.f32.bf16.bf16.f32 "
        "{%0,%1,%2,%3}, {%4,%5,%6,%7}, {%8,%9}, {%0,%1,%2,%3};"
        : "+f"(d[0]), "+f"(d[1]), "+f"(d[2]), "+f"(d[3])
        : "r"(a[0]), "r"(a[1]), "r"(a[2]), "r"(a[3]), "r"(b[0]), "r"(b[1]));
}
#define CPA16(dst, src) asm volatile("cp.async.cg.shared.global [%0], [%1], 16;" :: "r"(dst), "l"(src))
#define CPA_COMMIT()    asm volatile("cp.async.commit_group;" ::: "memory")
#define CPA_WAIT(n)     asm volatile("cp.async.wait_group %0;" :: "n"(n) : "memory")

// ---------------- K_wt: split-transpose in_proj_w (256x1024) -> [n][k] bf16 --
__global__ void k_wt(const float* __restrict__ W) {
    __shared__ float t[32][33];
    int n0 = blockIdx.x * 32, k0 = blockIdx.y * 32;
    int x = threadIdx.x, y0 = threadIdx.y;
    for (int yy = y0; yy < 32; yy += 8) t[yy][x] = W[(k0 + yy) * 1024 + n0 + x];
    __syncthreads();
    for (int yy = y0; yy < 32; yy += 8) {
        float v = t[x][yy];
        __nv_bfloat16 h = __float2bfloat16(v);
        __nv_bfloat16 l = __float2bfloat16(v - __bfloat162float(h));
        g_WtH[(size_t)(n0 + yy) * 256 + k0 + x] = h;
        g_WtL[(size_t)(n0 + yy) * 256 + k0 + x] = l;
    }
}

// ---------------- K_wc: Wc^T[c][d] = sum_k mow[d][k]*outp_w[k][c], split ----
__global__ void k_wc(const float* __restrict__ mw, const float* __restrict__ ow) {
    int d = blockIdx.x;      // 512
    int e = threadIdx.x;     // 128 (c)
    float acc = 0.f;
#pragma unroll 8
    for (int c = 0; c < 256; ++c)
        acc = fmaf(mw[d * 256 + c], ow[c * 128 + e], acc);
    __nv_bfloat16 h = __float2bfloat16(acc);
    __nv_bfloat16 l = __float2bfloat16(acc - __bfloat162float(h));
    g_WcH[(size_t)e * 512 + d] = h;
    g_WcL[(size_t)e * 512 + d] = l;
}

// ---------------- K1: concat + layernorm -> bf16 hi/lo (c,m) ----------------
__global__ void k_ln(const float* __restrict__ in1, const float* __restrict__ in2,
                     const float* __restrict__ gg, const float* __restrict__ bb) {
    __shared__ float sg[256], sb[256];
    int tid = threadIdx.x;
    for (int c = tid; c < 256; c += 128) { sg[c] = gg[c]; sb[c] = bb[c]; }
    __syncthreads();

    int m = blockIdx.x * 128 + tid;
    int b = m >> 12, t = m & 4095;
    const float* p1 = in1 + (size_t)b * 128 * 4096 + t;
    const float* p2 = in2 + (size_t)b * 128 * 4096 + t;

    float s = 0.f, s2 = 0.f;
#pragma unroll 4
    for (int c = 0; c < 128; ++c) { float v = p1[c * 4096]; s += v; s2 += v * v; }
#pragma unroll 4
    for (int c = 0; c < 128; ++c) { float v = p2[c * 4096]; s += v; s2 += v * v; }
    float mu = s * (1.f / 256.f);
    float var = s2 * (1.f / 256.f) - mu * mu;
    float rs = rsqrtf(var + 1e-5f);
#pragma unroll 4
    for (int c = 0; c < 256; ++c) {
        float v = (c < 128) ? p1[c * 4096] : p2[(c - 128) * 4096];
        float o = (v - mu) * rs * sg[c] + sb[c];
        __nv_bfloat16 h = __float2bfloat16(o);
        __nv_bfloat16 l = __float2bfloat16(o - __bfloat162float(h));
        g_XnH[(size_t)c * M_TOT + m] = h;
        g_XnL[(size_t)c * M_TOT + m] = l;
    }
}

// ---------------- warp-MMA GEMM: split bf16, cp.async 2-stage pipeline -------
// D[row][m] = sum_k A[row][k]*B[k][m], 3-term split.
// A: bf16 H/L [rows][KT] K-major. B: bf16 H/L (k,m) rows of M_TOT.
// Stage = 64 k. Stage layout: +0 A_H(16K), +16K A_L, +32K B_H(16K), +48K B_L.
#define STG_SZ 65536
#define SMEM_MMA 131072

template<int KT, bool IS_OUT>
__global__ void __launch_bounds__(256) k_mma(
    const __nv_bfloat16* __restrict__ AH, const __nv_bfloat16* __restrict__ AL,
    const __nv_bfloat16* __restrict__ BH, const __nv_bfloat16* __restrict__ BL,
    float* __restrict__ outp, const float* __restrict__ bias)
{
    extern __shared__ __align__(16) char sm[];
    const int tid = threadIdx.x;
    const int lane = tid & 31, wid = tid >> 5;
    const int wr = wid & 1, wc = wid >> 1;     // 2 x 4 warps
    const int m0 = blockIdx.x * 128, n0 = blockIdx.y * 128;
    const uint32_t smb = smem_u32(sm);
    const int NK = KT / 64;

    float acc[4][4][4];
#pragma unroll
    for (int i = 0; i < 4; ++i)
#pragma unroll
        for (int j = 0; j < 4; ++j)
#pragma unroll
            for (int p = 0; p < 4; ++p) acc[i][j][p] = 0.f;

    // stage issue: 16B cp.async x (4 A_H + 4 A_L + 4 B_H + 4 B_L) per thread
    auto stage = [&](int kc, int stg) {
        uint32_t base = smb + stg * STG_SZ;
#pragma unroll
        for (int it = 0; it < 4; ++it) {
            int cid = it * 256 + tid;          // 0..1023
            int row = cid >> 3, seg = cid & 7;
            size_t gof = (size_t)(n0 + row) * KT + kc * 64 + seg * 8;
            uint32_t off = row * 128 + ((seg ^ (row & 7)) << 4);
            CPA16(base + off, AH + gof);
            CPA16(base + 16384 + off, AL + gof);
        }
#pragma unroll
        for (int it = 0; it < 4; ++it) {
            int cid = it * 256 + tid;
            int k = cid >> 4, mseg = cid & 15;
            size_t gof = (size_t)(kc * 64 + k) * M_TOT + m0 + mseg * 8;
            uint32_t off = k * 256 + ((mseg ^ (k & 7)) << 4);
            CPA16(base + 32768 + off, BH + gof);
            CPA16(base + 49152 + off, BL + gof);
        }
    };

    stage(0, 0);
    CPA_COMMIT();

    for (int kc = 0; kc < NK; ++kc) {
        if (kc + 1 < NK) { stage(kc + 1, (kc + 1) & 1); CPA_COMMIT(); CPA_WAIT(1); }
        else CPA_WAIT(0);
        __syncthreads();

        uint32_t sa_h = smb + (kc & 1) * STG_SZ;
        uint32_t sa_l = sa_h + 16384;
        uint32_t sb_h = sa_h + 32768;
        uint32_t sb_l = sa_h + 49152;

#pragma unroll
        for (int ks = 0; ks < 4; ++ks) {
            uint32_t afh[4][4], afl[4][4];
            {
                int row = wr * 64 + (lane & 7) + ((lane >> 3) & 1) * 8;
                int seg = ks * 2 + (lane >> 4);
#pragma unroll
                for (int rt = 0; rt < 4; ++rt) {
                    int r = row + rt * 16;
                    uint32_t off = r * 128 + ((seg ^ (r & 7)) << 4);
                    ldsm4(afh[rt], sa_h + off);
                    ldsm4(afl[rt], sa_l + off);
                }
            }
            uint32_t bfh[4][2], bfl[4][2];
            {
                int k = ks * 16 + (lane & 7) + ((lane >> 3) & 1) * 8;
#pragma unroll
                for (int half = 0; half < 2; ++half) {
                    int mseg = wc * 4 + half * 2 + (lane >> 4);
                    uint32_t off = k * 256 + ((mseg ^ (k & 7)) << 4);
                    uint32_t r[4];
                    ldsm4t(r, sb_h + off);
                    bfh[half * 2][0] = r[0]; bfh[half * 2][1] = r[1];
                    bfh[half * 2 + 1][0] = r[2]; bfh[half * 2 + 1][1] = r[3];
                    ldsm4t(r, sb_l + off);
                    bfl[half * 2][0] = r[0]; bfl[half * 2][1] = r[1];
                    bfl[half * 2 + 1][0] = r[2]; bfl[half * 2 + 1][1] = r[3];
                }
            }
#pragma unroll
            for (int rt = 0; rt < 4; ++rt)
#pragma unroll
                for (int ct = 0; ct < 4; ++ct) {
                    mma_bf16(acc[rt][ct], afh[rt], bfh[ct]);
                    mma_bf16(acc[rt][ct], afh[rt], bfl[ct]);
                    mma_bf16(acc[rt][ct], afl[rt], bfh[ct]);
                }
        }
        __syncthreads();
    }

    // ---- epilogue ----
#pragma unroll
    for (int rt = 0; rt < 4; ++rt) {
        int row0 = n0 + wr * 64 + rt * 16 + (lane >> 2);
        int row1 = row0 + 8;
        float b0 = 0.f, b1 = 0.f;
        if (IS_OUT) { b0 = bias[row0]; b1 = bias[row1]; }
#pragma unroll
        for (int ct = 0; ct < 4; ++ct) {
            int col = m0 + wc * 32 + ct * 8 + (lane & 3) * 2;
            float2 v0 = make_float2(acc[rt][ct][0] + b0, acc[rt][ct][1] + b0);
            float2 v1 = make_float2(acc[rt][ct][2] + b1, acc[rt][ct][3] + b1);
            if (IS_OUT) {
                int bb = col >> 12, t = col & 4095;
                *(float2*)&outp[((size_t)(bb * 128 + row0) << 12) + t] = v0;
                *(float2*)&outp[((size_t)(bb * 128 + row1) << 12) + t] = v1;
            } else {
                *(float2*)&outp[(size_t)row0 * M_TOT + col] = v0;
                *(float2*)&outp[(size_t)row1 * M_TOT + col] = v1;
            }
        }
    }
}

// ---------------- K3: causal dwconv(4) + bias + silu, float4 ----------------
__global__ void k_conv(const float* __restrict__ cw, const float* __restrict__ cb) {
    int d = blockIdx.y;
    int m4 = (blockIdx.x * 256 + threadIdx.x) * 4;
    int t4 = m4 & 4095;
    const float* row = g_xz + (size_t)d * M_TOT;
    float4 v = *(const float4*)&row[m4];
    float4 vp = (t4 == 0) ? make_float4(0.f, 0.f, 0.f, 0.f)
                          : *(const float4*)&row[m4 - 4];
    float w0 = cw[d * 4 + 0], w1 = cw[d * 4 + 1], w2 = cw[d * 4 + 2], w3 = cw[d * 4 + 3];
    float bia = cb[d];
    float4 o;
    o.x = bia + w3 * v.x + w2 * vp.w + w1 * vp.z + w0 * vp.y;
    o.y = bia + w3 * v.y + w2 * v.x + w1 * vp.w + w0 * vp.z;
    o.z = bia + w3 * v.z + w2 * v.y + w1 * v.x + w0 * vp.w;
    o.w = bia + w3 * v.w + w2 * v.z + w1 * v.y + w0 * v.x;
    o.x = o.x / (1.f + __expf(-o.x));
    o.y = o.y / (1.f + __expf(-o.y));
    o.z = o.z / (1.f + __expf(-o.z));
    o.w = o.w / (1.f + __expf(-o.w));
    *(float4*)&g_xs[(size_t)d * M_TOT + m4] = o;
}

// ---------------- K4: x_proj + dt_proj fused --------------------------------
// phase 1: x_dbl(m,48) = xs^T @ xw; dt (j<16) kept in smem.
// phase 2: delta(d,m) = softplus(dt @ dtw + db).
__global__ void __launch_bounds__(256) k_xproj(const float* __restrict__ xw,
                                               const float* __restrict__ dtw,
                                               const float* __restrict__ db) {
    __shared__ __align__(16) float Ash[32][128];
    __shared__ float Wsh[32][48];
    __shared__ float sdt[128][17];
    __shared__ float shw[16][128];
    __shared__ float shb[128];
    int tid = threadIdx.x;
    int m0 = blockIdx.x * 128;
    int tj = tid >> 5, tm = tid & 31;
    float acc[6][4] = {};

    for (int k0 = 0; k0 < 512; k0 += 32) {
#pragma unroll
        for (int r = 0; r < 4; ++r) {
            int lin = r * 256 + tid;
            int row = lin >> 5, c4 = (lin & 31) << 2;
            *(float4*)&Ash[row][c4] = *(const float4*)&g_xs[(size_t)(k0 + row) * M_TOT + m0 + c4];
        }
#pragma unroll
        for (int r = 0; r < 6; ++r) {
            int lin = r * 256 + tid;
            int row = lin / 48, col = lin % 48;
            Wsh[row][col] = xw[(k0 + row) * 48 + col];
        }
        __syncthreads();
#pragma unroll
        for (int kk = 0; kk < 32; ++kk) {
            float a[4];
            *(float4*)&a[0] = *(const float4*)&Ash[kk][tm * 4];
#pragma unroll
            for (int q = 0; q < 6; ++q) {
                float w = Wsh[kk][tj * 6 + q];
#pragma unroll
                for (int p = 0; p < 4; ++p) acc[q][p] = fmaf(w, a[p], acc[q][p]);
            }
        }
        __syncthreads();
    }
#pragma unroll
    for (int p = 0; p < 4; ++p) {
        int mloc = tm * 4 + p;
#pragma unroll
        for (int q = 0; q < 6; ++q) {
            int j = tj * 6 + q;
            if (j < 16) sdt[mloc][j] = acc[q][p];
            else g_xdbl[(size_t)(m0 + mloc) * 48 + j] = acc[q][p];
        }
    }
    __syncthreads();

    // phase 2: delta = softplus(dt @ dtw + db), store (d, m)
    int mloc = tid & 127, half = tid >> 7;
    float rr[16];
#pragma unroll
    for (int r = 0; r < 16; ++r) rr[r] = sdt[mloc][r];

    for (int dq = 0; dq < 4; ++dq) {
#pragma unroll
        for (int r = 0; r < 8; ++r) {
            int lin = r * 256 + tid;
            int row = lin >> 7, col = lin & 127;
            shw[row][col] = dtw[row * 512 + dq * 128 + col];
        }
        if (tid < 128) shb[tid] = db[dq * 128 + tid];
        __syncthreads();
#pragma unroll 4
        for (int dd = 0; dd < 64; ++dd) {
            int dcol = half * 64 + dd;
            float a = shb[dcol];
#pragma unroll
            for (int r = 0; r < 16; ++r) a = fmaf(rr[r], shw[r][dcol], a);
            float sp = (a > 20.f) ? a : log1pf(__expf(a));
            g_delta[(size_t)(dq * 128 + dcol) * M_TOT + m0 + mloc] = sp;
        }
        __syncthreads();
    }
}

// ---------------- chunked selective scan, 4-lane n-groups --------------------
// lane l owns n = 4l..4l+3. group = 4 lanes = one (b,d) pair.
__global__ void __launch_bounds__(256) k_scanA(const float* __restrict__ A_log) {
    int tid = threadIdx.x;
    int l = tid & 3;
    int p = blockIdx.x * 64 + (tid >> 2);      // b*512 + d
    int b = p >> 9, d = p & 511;
    int c = blockIdx.y;
    int t0 = c * CLEN;

    float A0 = -__expf(A_log[d * 16 + 4 * l + 0]);
    float A1 = -__expf(A_log[d * 16 + 4 * l + 1]);
    float A2 = -__expf(A_log[d * 16 + 4 * l + 2]);
    float A3 = -__expf(A_log[d * 16 + 4 * l + 3]);

    const float* pdelta = g_delta + (size_t)d * M_TOT + b * L_SEQ + t0;
    const float* px     = g_xs    + (size_t)d * M_TOT + b * L_SEQ + t0;
    const float* pB     = g_xdbl  + (size_t)(b * L_SEQ + t0) * 48 + 16 + 4 * l;

    float h0 = 0.f, h1 = 0.f, h2 = 0.f, h3 = 0.f;
    float P0 = 1.f, P1 = 1.f, P2 = 1.f, P3 = 1.f;
#pragma unroll 2
    for (int t = 0; t < CLEN; t += 4) {
        float4 dl4 = *(const float4*)&pdelta[t];
        float4 xv4 = *(const float4*)&px[t];
#pragma unroll
        for (int s = 0; s < 4; ++s) {
            float dl = (&dl4.x)[s];
            float xv = (&xv4.x)[s];
            float4 Bv = *(const float4*)&pB[(t + s) * 48];
            float e0 = __expf(dl * A0), e1 = __expf(dl * A1);
            float e2 = __expf(dl * A2), e3 = __expf(dl * A3);
            float du = dl * xv;
            h0 = fmaf(h0, e0, du * Bv.x);
            h1 = fmaf(h1, e1, du * Bv.y);
            h2 = fmaf(h2, e2, du * Bv.z);
            h3 = fmaf(h3, e3, du * Bv.w);
            P0 *= e0; P1 *= e1; P2 *= e2; P3 *= e3;
        }
    }
    int idx = c * 32768 + p * 16 + 4 * l;
    *(float4*)&g_P[idx]  = make_float4(P0, P1, P2, P3);
    *(float4*)&g_Lh[idx] = make_float4(h0, h1, h2, h3);
}

// Phase B: scan across chunks. thread = (p, n). [c][p][n]: coalesced.
__global__ void __launch_bounds__(256) k_scanB() {
    int gid = blockIdx.x * 256 + threadIdx.x;   // 0..32767
    float h = 0.f;
#pragma unroll 8
    for (int c = 0; c < NCHUNK; ++c) {
        int idx = c * 32768 + gid;
        g_H[idx] = h;
        h = fmaf(h, g_P[idx], g_Lh[idx]);
    }
}

// Phase C: recompute from h_start, reduce 4 lanes, gate, store y hi/lo bf16.
__global__ void __launch_bounds__(256) k_scanC(const float* __restrict__ A_log,
                                               const float* __restrict__ Dp_) {
    int tid = threadIdx.x;
    int l = tid & 3;
    int p = blockIdx.x * 64 + (tid >> 2);
    int b = p >> 9, d = p & 511;
    int c = blockIdx.y;
    int t0 = c * CLEN;

    float A0 = -__expf(A_log[d * 16 + 4 * l + 0]);
    float A1 = -__expf(A_log[d * 16 + 4 * l + 1]);
    float A2 = -__expf(A_log[d * 16 + 4 * l + 2]);
    float A3 = -__expf(A_log[d * 16 + 4 * l + 3]);
    float Dv = Dp_[d];

    const float* pdelta = g_delta + (size_t)d * M_TOT + b * L_SEQ + t0;
    const float* px     = g_xs    + (size_t)d * M_TOT + b * L_SEQ + t0;
    const float* pz     = g_xz    + (size_t)(512 + d) * M_TOT + b * L_SEQ + t0;
    const float* pB     = g_xdbl  + (size_t)(b * L_SEQ + t0) * 48 + 16 + 4 * l;
    const float* pC     = pB + 16;
    __nv_bfloat16* pyH  = g_yH    + (size_t)d * M_TOT + b * L_SEQ + t0;
    __nv_bfloat16* pyL  = g_yL    + (size_t)d * M_TOT + b * L_SEQ + t0;

    int idx = c * 32768 + p * 16 + 4 * l;
    float4 hh = *(const float4*)&g_H[idx];
    float h0 = hh.x, h1 = hh.y, h2 = hh.z, h3 = hh.w;

#pragma unroll 2
    for (int t = 0; t < CLEN; t += 4) {
        float4 dl4 = *(const float4*)&pdelta[t];
        float4 xv4 = *(const float4*)&px[t];
        float4 zv4 = *(const float4*)&pz[t];
#pragma unroll
        for (int s = 0; s < 4; ++s) {
            float dl = (&dl4.x)[s];
            float xv = (&xv4.x)[s];
            float4 Bv = *(const float4*)&pB[(t + s) * 48];
            float4 Cv = *(const float4*)&pC[(t + s) * 48];
            float e0 = __expf(dl * A0), e1 = __expf(dl * A1);
            float e2 = __expf(dl * A2), e3 = __expf(dl * A3);
            float du = dl * xv;
            h0 = fmaf(h0, e0, du * Bv.x);
            h1 = fmaf(h1, e1, du * Bv.y);
            h2 = fmaf(h2, e2, du * Bv.z);
            h3 = fmaf(h3, e3, du * Bv.w);
            float pr = h0 * Cv.x;
            pr = fmaf(h1, Cv.y, pr);
            pr = fmaf(h2, Cv.z, pr);
            pr = fmaf(h3, Cv.w, pr);
            pr += __shfl_xor_sync(0xffffffffu, pr, 1);
            pr += __shfl_xor_sync(0xffffffffu, pr, 2);
            if (l == 0) {
                float zv = (&zv4.x)[s];
                float yv = fmaf(xv, Dv, pr);
                yv = yv * zv * (1.f / (1.f + __expf(-zv)));
                __nv_bfloat16 yh = __float2bfloat16(yv);
                __nv_bfloat16 yl = __float2bfloat16(yv - __bfloat162float(yh));
                pyH[t + s] = yh;
                pyL[t + s] = yl;
            }
        }
    }
}

// ---------------- launch -----------------------------------------------------
extern "C" void kernel_launch(void* const* d_in, const int* in_sizes, int n_in,
                              void* d_out, int out_size) {
    const float* input  = (const float*)d_in[0];
    const float* input2 = (const float*)d_in[1];
    const float* ln_g   = (const float*)d_in[2];
    const float* ln_b   = (const float*)d_in[3];
    const float* outp_w = (const float*)d_in[4];
    const float* outp_b = (const float*)d_in[5];
    const float* inproj = (const float*)d_in[6];
    const float* conv_w = (const float*)d_in[7];
    const float* conv_b = (const float*)d_in[8];
    const float* xproj  = (const float*)d_in[9];
    const float* dtw    = (const float*)d_in[10];
    const float* dtb    = (const float*)d_in[11];
    const float* A_log  = (const float*)d_in[12];
    const float* Dp     = (const float*)d_in[13];
    const float* mow    = (const float*)d_in[14];
    float* out = (float*)d_out;

    __nv_bfloat16 *wtH, *wtL, *wcH, *wcL, *xnH, *xnL, *yH, *yL;
    float *xz;
    cudaGetSymbolAddress((void**)&wtH, g_WtH);
    cudaGetSymbolAddress((void**)&wtL, g_WtL);
    cudaGetSymbolAddress((void**)&wcH, g_WcH);
    cudaGetSymbolAddress((void**)&wcL, g_WcL);
    cudaGetSymbolAddress((void**)&xnH, g_XnH);
    cudaGetSymbolAddress((void**)&xnL, g_XnL);
    cudaGetSymbolAddress((void**)&yH, g_yH);
    cudaGetSymbolAddress((void**)&yL, g_yL);
    cudaGetSymbolAddress((void**)&xz, g_xz);

    cudaFuncSetAttribute(k_mma<256, false>,
                         cudaFuncAttributeMaxDynamicSharedMemorySize, SMEM_MMA);
    cudaFuncSetAttribute(k_mma<512, true>,
                         cudaFuncAttributeMaxDynamicSharedMemorySize, SMEM_MMA);

    k_wt<<<dim3(32, 8), dim3(32, 8)>>>(inproj);
    k_wc<<<512, 128>>>(mow, outp_w);
    k_ln<<<128, 128>>>(input, input2, ln_g, ln_b);
    k_mma<256, false><<<dim3(128, 8), 256, SMEM_MMA>>>(wtH, wtL, xnH, xnL, xz, nullptr);
    k_conv<<<dim3(16, 512), 256>>>(conv_w, conv_b);
    k_xproj<<<128, 256>>>(xproj, dtw, dtb);
    k_scanA<<<dim3(32, 64), 256>>>(A_log);
    k_scanB<<<128, 256>>>();
    k_scanC<<<dim3(32, 64), 256>>>(A_log, Dp);
    k_mma<512, true><<<dim3(128, 1), 256, SMEM_MMA>>>(wcH, wcL, yH, yL, out, outp_b);
}

// round 7
// speedup vs baseline: 6.3999x; 1.3378x over previous
#include <cuda_runtime.h>
#include <cuda_bf16.h>
#include <cstdint>

typedef unsigned long long ull;

#define M_TOT 16384   // B * L
#define L_SEQ 4096
#define NCHUNK 64
#define CLEN 64
#define LOG2E 1.4426950408889634f
#define SPITCH 68     // scan smem row pitch (floats): 16B-aligned, conflict-free

// ---------------- scratch ----------------------------------------------------
__device__ __align__(16) float g_xz[1024 * M_TOT];    // in_proj out (n,m); n>=512 = z
__device__ __align__(16) float g_xs[512 * M_TOT];     // conv+silu, (d, m)
__device__ __align__(16) float g_xdbl[M_TOT * 48];    // x_proj out, (m, j)
__device__ __align__(16) float g_delta[512 * M_TOT];  // softplus, (d, m)
__device__ __align__(16) float g_P[NCHUNK * 2048 * 16];
__device__ __align__(16) float g_Lh[NCHUNK * 2048 * 16];
__device__ __align__(16) float g_H[NCHUNK * 2048 * 16];
__device__ __align__(16) __nv_bfloat16 g_XnH[256 * M_TOT];
__device__ __align__(16) __nv_bfloat16 g_XnL[256 * M_TOT];
__device__ __align__(16) __nv_bfloat16 g_yH[512 * M_TOT];
__device__ __align__(16) __nv_bfloat16 g_yL[512 * M_TOT];
__device__ __align__(16) __nv_bfloat16 g_WtH[1024 * 256];
__device__ __align__(16) __nv_bfloat16 g_WtL[1024 * 256];
__device__ __align__(16) __nv_bfloat16 g_WcH[128 * 512];
__device__ __align__(16) __nv_bfloat16 g_WcL[128 * 512];

// ---------------- helpers ----------------------------------------------------
__device__ __forceinline__ uint32_t smem_u32(const void* p) {
    uint32_t a;
    asm("{ .reg .u64 t; cvta.to.shared.u64 t, %1; cvt.u32.u64 %0, t; }" : "=r"(a) : "l"(p));
    return a;
}
__device__ __forceinline__ float ex2(float x) {
    float r;
    asm("ex2.approx.f32 %0, %1;" : "=f"(r) : "f"(x));
    return r;
}
__device__ __forceinline__ void ldsm4(uint32_t* r, uint32_t addr) {
    asm volatile("ldmatrix.sync.aligned.m8n8.x4.shared.b16 {%0,%1,%2,%3}, [%4];"
        : "=r"(r[0]), "=r"(r[1]), "=r"(r[2]), "=r"(r[3]) : "r"(addr));
}
__device__ __forceinline__ void ldsm4t(uint32_t* r, uint32_t addr) {
    asm volatile("ldmatrix.sync.aligned.m8n8.x4.trans.shared.b16 {%0,%1,%2,%3}, [%4];"
        : "=r"(r[0]), "=r"(r[1]), "=r"(r[2]), "=r"(r[3]) : "r"(addr));
}
__device__ __forceinline__ void mma_bf16(float* d, const uint32_t* a, const uint32_t* b) {
    asm volatile("mma.sync.aligned.m16n8k16.row.col.f32.bf16.bf16.f32 "
        "{%0,%1,%2,%3}, {%4,%5,%6,%7}, {%8,%9}, {%0,%1,%2,%3};"
        : "+f"(d[0]), "+f"(d[1]), "+f"(d[2]), "+f"(d[3])
        : "r"(a[0]), "r"(a[1]), "r"(a[2]), "r"(a[3]), "r"(b[0]), "r"(b[1]));
}
#define CPA16(dst, src) asm volatile("cp.async.cg.shared.global [%0], [%1], 16;" :: "r"(dst), "l"(src))
#define CPA_COMMIT()    asm volatile("cp.async.commit_group;" ::: "memory")
#define CPA_WAIT(n)     asm volatile("cp.async.wait_group %0;" :: "n"(n) : "memory")

// ---------------- K_wt: split-transpose in_proj_w -> [n][k] bf16 ------------
__global__ void k_wt(const float* __restrict__ W) {
    __shared__ float t[32][33];
    int n0 = blockIdx.x * 32, k0 = blockIdx.y * 32;
    int x = threadIdx.x, y0 = threadIdx.y;
    for (int yy = y0; yy < 32; yy += 8) t[yy][x] = W[(k0 + yy) * 1024 + n0 + x];
    __syncthreads();
    for (int yy = y0; yy < 32; yy += 8) {
        float v = t[x][yy];
        __nv_bfloat16 h = __float2bfloat16(v);
        __nv_bfloat16 l = __float2bfloat16(v - __bfloat162float(h));
        g_WtH[(size_t)(n0 + yy) * 256 + k0 + x] = h;
        g_WtL[(size_t)(n0 + yy) * 256 + k0 + x] = l;
    }
}

// ---------------- K_wc: (mow @ outp_w)^T split ------------------------------
__global__ void k_wc(const float* __restrict__ mw, const float* __restrict__ ow) {
    int d = blockIdx.x, e = threadIdx.x;
    float acc = 0.f;
#pragma unroll 8
    for (int c = 0; c < 256; ++c)
        acc = fmaf(mw[d * 256 + c], ow[c * 128 + e], acc);
    __nv_bfloat16 h = __float2bfloat16(acc);
    __nv_bfloat16 l = __float2bfloat16(acc - __bfloat162float(h));
    g_WcH[(size_t)e * 512 + d] = h;
    g_WcL[(size_t)e * 512 + d] = l;
}

// ---------------- K1: concat + LN, 4 threads per token ----------------------
__global__ void __launch_bounds__(256) k_ln(const float* __restrict__ in1,
                                            const float* __restrict__ in2,
                                            const float* __restrict__ gg,
                                            const float* __restrict__ bb) {
    __shared__ float sg[256], sb[256];
    __shared__ float red[2][4][64];
    int tid = threadIdx.x;
    int q = tid >> 6, ml = tid & 63;
    sg[tid] = gg[tid]; sb[tid] = bb[tid];

    int m = blockIdx.x * 64 + ml;
    int b = m >> 12, t = m & 4095;
    const float* src = ((q < 2) ? in1 : in2) + (size_t)b * 128 * 4096 + t;
    int c0 = (q & 1) * 64;

    float vals[64];
    float s = 0.f, s2 = 0.f;
#pragma unroll
    for (int i = 0; i < 64; ++i) {
        float v = src[(size_t)(c0 + i) * 4096];
        vals[i] = v; s += v; s2 += v * v;
    }
    red[0][q][ml] = s; red[1][q][ml] = s2;
    __syncthreads();
    s  = red[0][0][ml] + red[0][1][ml] + red[0][2][ml] + red[0][3][ml];
    s2 = red[1][0][ml] + red[1][1][ml] + red[1][2][ml] + red[1][3][ml];
    float mu = s * (1.f / 256.f);
    float var = s2 * (1.f / 256.f) - mu * mu;
    float rs = rsqrtf(var + 1e-5f);

    int cbase = q * 64;
#pragma unroll
    for (int i = 0; i < 64; ++i) {
        int c = cbase + i;
        float o = (vals[i] - mu) * rs * sg[c] + sb[c];
        __nv_bfloat16 h = __float2bfloat16(o);
        __nv_bfloat16 l = __float2bfloat16(o - __bfloat162float(h));
        g_XnH[(size_t)c * M_TOT + m] = h;
        g_XnL[(size_t)c * M_TOT + m] = l;
    }
}

// ---------------- warp-MMA GEMM: split bf16, cp.async 3-stage ----------------
#define STG_SZ 65536
#define SMEM_MMA 196608

template<int KT, bool IS_OUT>
__global__ void __launch_bounds__(256) k_mma(
    const __nv_bfloat16* __restrict__ AH, const __nv_bfloat16* __restrict__ AL,
    const __nv_bfloat16* __restrict__ BH, const __nv_bfloat16* __restrict__ BL,
    float* __restrict__ outp, const float* __restrict__ bias)
{
    extern __shared__ __align__(16) char sm[];
    const int tid = threadIdx.x;
    const int lane = tid & 31, wid = tid >> 5;
    const int wr = wid & 1, wc = wid >> 1;
    const int m0 = blockIdx.x * 128, n0 = blockIdx.y * 128;
    const uint32_t smb = smem_u32(sm);
    const int NK = KT / 64;

    float acc[4][4][4];
#pragma unroll
    for (int i = 0; i < 4; ++i)
#pragma unroll
        for (int j = 0; j < 4; ++j)
#pragma unroll
            for (int p = 0; p < 4; ++p) acc[i][j][p] = 0.f;

    auto stage = [&](int kc, int stg) {
        uint32_t base = smb + stg * STG_SZ;
#pragma unroll
        for (int it = 0; it < 4; ++it) {
            int cid = it * 256 + tid;
            int row = cid >> 3, seg = cid & 7;
            size_t gof = (size_t)(n0 + row) * KT + kc * 64 + seg * 8;
            uint32_t off = row * 128 + ((seg ^ (row & 7)) << 4);
            CPA16(base + off, AH + gof);
            CPA16(base + 16384 + off, AL + gof);
        }
#pragma unroll
        for (int it = 0; it < 4; ++it) {
            int cid = it * 256 + tid;
            int k = cid >> 4, mseg = cid & 15;
            size_t gof = (size_t)(kc * 64 + k) * M_TOT + m0 + mseg * 8;
            uint32_t off = k * 256 + ((mseg ^ (k & 7)) << 4);
            CPA16(base + 32768 + off, BH + gof);
            CPA16(base + 49152 + off, BL + gof);
        }
    };

    stage(0, 0); CPA_COMMIT();
    if (NK > 1) { stage(1, 1); CPA_COMMIT(); }

    for (int kc = 0; kc < NK; ++kc) {
        if (kc + 1 < NK) CPA_WAIT(1); else CPA_WAIT(0);
        __syncthreads();
        if (kc + 2 < NK) { stage(kc + 2, (kc + 2) % 3); CPA_COMMIT(); }

        uint32_t sa_h = smb + (kc % 3) * STG_SZ;
        uint32_t sa_l = sa_h + 16384;
        uint32_t sb_h = sa_h + 32768;
        uint32_t sb_l = sa_h + 49152;

#pragma unroll
        for (int ks = 0; ks < 4; ++ks) {
            uint32_t afh[4][4], afl[4][4];
            {
                int row = wr * 64 + (lane & 7) + ((lane >> 3) & 1) * 8;
                int seg = ks * 2 + (lane >> 4);
#pragma unroll
                for (int rt = 0; rt < 4; ++rt) {
                    int r = row + rt * 16;
                    uint32_t off = r * 128 + ((seg ^ (r & 7)) << 4);
                    ldsm4(afh[rt], sa_h + off);
                    ldsm4(afl[rt], sa_l + off);
                }
            }
            uint32_t bfh[4][2], bfl[4][2];
            {
                int k = ks * 16 + (lane & 7) + ((lane >> 3) & 1) * 8;
#pragma unroll
                for (int half = 0; half < 2; ++half) {
                    int mseg = wc * 4 + half * 2 + (lane >> 4);
                    uint32_t off = k * 256 + ((mseg ^ (k & 7)) << 4);
                    uint32_t r[4];
                    ldsm4t(r, sb_h + off);
                    bfh[half * 2][0] = r[0]; bfh[half * 2][1] = r[1];
                    bfh[half * 2 + 1][0] = r[2]; bfh[half * 2 + 1][1] = r[3];
                    ldsm4t(r, sb_l + off);
                    bfl[half * 2][0] = r[0]; bfl[half * 2][1] = r[1];
                    bfl[half * 2 + 1][0] = r[2]; bfl[half * 2 + 1][1] = r[3];
                }
            }
#pragma unroll
            for (int rt = 0; rt < 4; ++rt)
#pragma unroll
                for (int ct = 0; ct < 4; ++ct) {
                    mma_bf16(acc[rt][ct], afh[rt], bfh[ct]);
                    mma_bf16(acc[rt][ct], afh[rt], bfl[ct]);
                    mma_bf16(acc[rt][ct], afl[rt], bfh[ct]);
                }
        }
    }

#pragma unroll
    for (int rt = 0; rt < 4; ++rt) {
        int row0 = n0 + wr * 64 + rt * 16 + (lane >> 2);
        int row1 = row0 + 8;
        float b0 = 0.f, b1 = 0.f;
        if (IS_OUT) { b0 = bias[row0]; b1 = bias[row1]; }
#pragma unroll
        for (int ct = 0; ct < 4; ++ct) {
            int col = m0 + wc * 32 + ct * 8 + (lane & 3) * 2;
            float2 v0 = make_float2(acc[rt][ct][0] + b0, acc[rt][ct][1] + b0);
            float2 v1 = make_float2(acc[rt][ct][2] + b1, acc[rt][ct][3] + b1);
            if (IS_OUT) {
                int bb = col >> 12, t = col & 4095;
                *(float2*)&outp[((size_t)(bb * 128 + row0) << 12) + t] = v0;
                *(float2*)&outp[((size_t)(bb * 128 + row1) << 12) + t] = v1;
            } else {
                *(float2*)&outp[(size_t)row0 * M_TOT + col] = v0;
                *(float2*)&outp[(size_t)row1 * M_TOT + col] = v1;
            }
        }
    }
}

// ---------------- K3: causal dwconv(4) + bias + silu, float4 ----------------
__global__ void k_conv(const float* __restrict__ cw, const float* __restrict__ cb) {
    int d = blockIdx.y;
    int m4 = (blockIdx.x * 256 + threadIdx.x) * 4;
    int t4 = m4 & 4095;
    const float* row = g_xz + (size_t)d * M_TOT;
    float4 v = *(const float4*)&row[m4];
    float4 vp = (t4 == 0) ? make_float4(0.f, 0.f, 0.f, 0.f)
                          : *(const float4*)&row[m4 - 4];
    float w0 = cw[d * 4 + 0], w1 = cw[d * 4 + 1], w2 = cw[d * 4 + 2], w3 = cw[d * 4 + 3];
    float bia = cb[d];
    float4 o;
    o.x = bia + w3 * v.x + w2 * vp.w + w1 * vp.z + w0 * vp.y;
    o.y = bia + w3 * v.y + w2 * v.x + w1 * vp.w + w0 * vp.z;
    o.z = bia + w3 * v.z + w2 * v.y + w1 * v.x + w0 * vp.w;
    o.w = bia + w3 * v.w + w2 * v.z + w1 * v.y + w0 * v.x;
    o.x = o.x / (1.f + __expf(-o.x));
    o.y = o.y / (1.f + __expf(-o.y));
    o.z = o.z / (1.f + __expf(-o.z));
    o.w = o.w / (1.f + __expf(-o.w));
    *(float4*)&g_xs[(size_t)d * M_TOT + m4] = o;
}

// ---------------- K4: x_proj + dt_proj fused, m-tile 64, grid 256 -----------
__global__ void __launch_bounds__(256) k_xproj(const float* __restrict__ xw,
                                               const float* __restrict__ dtw,
                                               const float* __restrict__ db) {
    __shared__ __align__(16) float Ash[32][64];
    __shared__ float Wsh[32][48];
    __shared__ float sdt[64][17];
    __shared__ float shw[16][128];
    __shared__ float shb[128];
    int tid = threadIdx.x;
    int m0 = blockIdx.x * 64;
    int tj = tid >> 5, tm = tid & 31;
    float acc[6][2] = {};

    for (int k0 = 0; k0 < 512; k0 += 32) {
#pragma unroll
        for (int r = 0; r < 2; ++r) {
            int lin = r * 256 + tid;
            int row = lin >> 4, c4 = (lin & 15) << 2;
            *(float4*)&Ash[row][c4] = *(const float4*)&g_xs[(size_t)(k0 + row) * M_TOT + m0 + c4];
        }
#pragma unroll
        for (int r = 0; r < 6; ++r) {
            int lin = r * 256 + tid;
            int row = lin / 48, col = lin % 48;
            Wsh[row][col] = xw[(k0 + row) * 48 + col];
        }
        __syncthreads();
#pragma unroll
        for (int kk = 0; kk < 32; ++kk) {
            float2 a = *(const float2*)&Ash[kk][tm * 2];
#pragma unroll
            for (int q = 0; q < 6; ++q) {
                float w = Wsh[kk][tj * 6 + q];
                acc[q][0] = fmaf(w, a.x, acc[q][0]);
                acc[q][1] = fmaf(w, a.y, acc[q][1]);
            }
        }
        __syncthreads();
    }
#pragma unroll
    for (int p = 0; p < 2; ++p) {
        int mloc = tm * 2 + p;
#pragma unroll
        for (int q = 0; q < 6; ++q) {
            int j = tj * 6 + q;
            if (j < 16) sdt[mloc][j] = acc[q][p];
            else g_xdbl[(size_t)(m0 + mloc) * 48 + j] = acc[q][p];
        }
    }
    __syncthreads();

    int mloc = tid & 63, dseg = tid >> 6;
    float rr[16];
#pragma unroll
    for (int r = 0; r < 16; ++r) rr[r] = sdt[mloc][r];

    for (int dq = 0; dq < 4; ++dq) {
#pragma unroll
        for (int r = 0; r < 8; ++r) {
            int lin = r * 256 + tid;
            int row = lin >> 7, col = lin & 127;
            shw[row][col] = dtw[row * 512 + dq * 128 + col];
        }
        if (tid < 128) shb[tid] = db[dq * 128 + tid];
        __syncthreads();
#pragma unroll 4
        for (int dd = 0; dd < 32; ++dd) {
            int dcol = dseg * 32 + dd;
            float a = shb[dcol];
#pragma unroll
            for (int r = 0; r < 16; ++r) a = fmaf(rr[r], shw[r][dcol], a);
            float sp = (a > 20.f) ? a : log1pf(__expf(a));
            g_delta[(size_t)(dq * 128 + dcol) * M_TOT + m0 + mloc] = sp;
        }
        __syncthreads();
    }
}

// ---------------- chunked scan, smem-staged (SPITCH=68: 16B-aligned rows) ----
__global__ void __launch_bounds__(256) k_scanA(const float* __restrict__ A_log) {
    __shared__ __align__(16) float sdl[64 * SPITCH];
    __shared__ __align__(16) float sx[64 * SPITCH];
    __shared__ __align__(16) float sB[64 * 16];
    int tid = threadIdx.x;
    int l = tid & 3, g = tid >> 2;
    int p0 = blockIdx.x * 64;
    int b = p0 >> 9, d0 = p0 & 511;
    int c = blockIdx.y;
    int t0 = c * CLEN;
    size_t rowbase = (size_t)b * L_SEQ + t0;

#pragma unroll
    for (int it = 0; it < 4; ++it) {
        int lin = it * 256 + tid;
        int row = lin >> 4, tq = (lin & 15) << 2;
        *(float4*)&sdl[row * SPITCH + tq] = *(const float4*)&g_delta[(size_t)(d0 + row) * M_TOT + rowbase + tq];
        *(float4*)&sx[row * SPITCH + tq]  = *(const float4*)&g_xs[(size_t)(d0 + row) * M_TOT + rowbase + tq];
    }
    {
        int t = tid >> 2, n4 = (tid & 3) << 2;
        *(float4*)&sB[t * 16 + n4] = *(const float4*)&g_xdbl[(rowbase + t) * 48 + 16 + n4];
    }
    int d = d0 + g;
    float A0 = -__expf(A_log[d * 16 + 4 * l + 0]) * LOG2E;
    float A1 = -__expf(A_log[d * 16 + 4 * l + 1]) * LOG2E;
    float A2 = -__expf(A_log[d * 16 + 4 * l + 2]) * LOG2E;
    float A3 = -__expf(A_log[d * 16 + 4 * l + 3]) * LOG2E;
    __syncthreads();

    float h0 = 0.f, h1 = 0.f, h2 = 0.f, h3 = 0.f, S = 0.f;
#pragma unroll 4
    for (int t = 0; t < CLEN; ++t) {
        float dl = sdl[g * SPITCH + t];
        float xv = sx[g * SPITCH + t];
        float4 Bv = *(const float4*)&sB[t * 16 + 4 * l];
        float e0 = ex2(dl * A0), e1 = ex2(dl * A1);
        float e2 = ex2(dl * A2), e3 = ex2(dl * A3);
        float du = dl * xv;
        h0 = fmaf(h0, e0, du * Bv.x);
        h1 = fmaf(h1, e1, du * Bv.y);
        h2 = fmaf(h2, e2, du * Bv.z);
        h3 = fmaf(h3, e3, du * Bv.w);
        S += dl;
    }
    int idx = c * 32768 + (p0 + g) * 16 + 4 * l;
    *(float4*)&g_P[idx]  = make_float4(ex2(A0 * S), ex2(A1 * S), ex2(A2 * S), ex2(A3 * S));
    *(float4*)&g_Lh[idx] = make_float4(h0, h1, h2, h3);
}

// Phase B: scan across chunks.
__global__ void __launch_bounds__(256) k_scanB() {
    int gid = blockIdx.x * 256 + threadIdx.x;
    float h = 0.f;
#pragma unroll 8
    for (int c = 0; c < NCHUNK; ++c) {
        int idx = c * 32768 + gid;
        g_H[idx] = h;
        h = fmaf(h, g_P[idx], g_Lh[idx]);
    }
}

// Phase C: recompute + gate + coalesced bf16 y store.
#define SMEM_SCANC ((4 * 64 * SPITCH + 2 * 64 * 16) * 4)
__global__ void __launch_bounds__(256) k_scanC(const float* __restrict__ A_log,
                                               const float* __restrict__ Dp_) {
    extern __shared__ __align__(16) float smc[];
    float* sdl = smc;                        // [64][SPITCH]
    float* sx  = sdl + 64 * SPITCH;
    float* sz  = sx  + 64 * SPITCH;
    float* sy  = sz  + 64 * SPITCH;          // [64][SPITCH]
    float* sB  = sy  + 64 * SPITCH;          // [64*16]
    float* sC  = sB  + 64 * 16;

    int tid = threadIdx.x;
    int l = tid & 3, g = tid >> 2;
    int p0 = blockIdx.x * 64;
    int b = p0 >> 9, d0 = p0 & 511;
    int c = blockIdx.y;
    int t0 = c * CLEN;
    size_t rowbase = (size_t)b * L_SEQ + t0;

#pragma unroll
    for (int it = 0; it < 4; ++it) {
        int lin = it * 256 + tid;
        int row = lin >> 4, tq = (lin & 15) << 2;
        *(float4*)&sdl[row * SPITCH + tq] = *(const float4*)&g_delta[(size_t)(d0 + row) * M_TOT + rowbase + tq];
        *(float4*)&sx[row * SPITCH + tq]  = *(const float4*)&g_xs[(size_t)(d0 + row) * M_TOT + rowbase + tq];
        *(float4*)&sz[row * SPITCH + tq]  = *(const float4*)&g_xz[(size_t)(512 + d0 + row) * M_TOT + rowbase + tq];
    }
    {
        int t = tid >> 2, n4 = (tid & 3) << 2;
        *(float4*)&sB[t * 16 + n4] = *(const float4*)&g_xdbl[(rowbase + t) * 48 + 16 + n4];
        *(float4*)&sC[t * 16 + n4] = *(const float4*)&g_xdbl[(rowbase + t) * 48 + 32 + n4];
    }
    int d = d0 + g;
    float A0 = -__expf(A_log[d * 16 + 4 * l + 0]) * LOG2E;
    float A1 = -__expf(A_log[d * 16 + 4 * l + 1]) * LOG2E;
    float A2 = -__expf(A_log[d * 16 + 4 * l + 2]) * LOG2E;
    float A3 = -__expf(A_log[d * 16 + 4 * l + 3]) * LOG2E;
    float Dv = Dp_[d];
    __syncthreads();

    int idx = c * 32768 + (p0 + g) * 16 + 4 * l;
    float4 hh = *(const float4*)&g_H[idx];
    float h0 = hh.x, h1 = hh.y, h2 = hh.z, h3 = hh.w;

#pragma unroll 4
    for (int t = 0; t < CLEN; ++t) {
        float dl = sdl[g * SPITCH + t];
        float xv = sx[g * SPITCH + t];
        float4 Bv = *(const float4*)&sB[t * 16 + 4 * l];
        float4 Cv = *(const float4*)&sC[t * 16 + 4 * l];
        float e0 = ex2(dl * A0), e1 = ex2(dl * A1);
        float e2 = ex2(dl * A2), e3 = ex2(dl * A3);
        float du = dl * xv;
        h0 = fmaf(h0, e0, du * Bv.x);
        h1 = fmaf(h1, e1, du * Bv.y);
        h2 = fmaf(h2, e2, du * Bv.z);
        h3 = fmaf(h3, e3, du * Bv.w);
        float pr = h0 * Cv.x;
        pr = fmaf(h1, Cv.y, pr);
        pr = fmaf(h2, Cv.z, pr);
        pr = fmaf(h3, Cv.w, pr);
        pr += __shfl_xor_sync(0xffffffffu, pr, 1);
        pr += __shfl_xor_sync(0xffffffffu, pr, 2);
        if (l == 0) {
            float zv = sz[g * SPITCH + t];
            float yv = fmaf(xv, Dv, pr);
            yv = yv * zv * (1.f / (1.f + __expf(-zv)));
            sy[g * SPITCH + t] = yv;
        }
    }
    __syncthreads();

#pragma unroll
    for (int i = 0; i < 16; ++i) {
        int elem = i * 256 + tid;
        int row = elem >> 6, t = elem & 63;
        float yv = sy[row * SPITCH + t];
        __nv_bfloat16 yh = __float2bfloat16(yv);
        __nv_bfloat16 yl = __float2bfloat16(yv - __bfloat162float(yh));
        size_t gof = (size_t)(d0 + row) * M_TOT + rowbase + t;
        g_yH[gof] = yh;
        g_yL[gof] = yl;
    }
}

// ---------------- launch -----------------------------------------------------
extern "C" void kernel_launch(void* const* d_in, const int* in_sizes, int n_in,
                              void* d_out, int out_size) {
    const float* input  = (const float*)d_in[0];
    const float* input2 = (const float*)d_in[1];
    const float* ln_g   = (const float*)d_in[2];
    const float* ln_b   = (const float*)d_in[3];
    const float* outp_w = (const float*)d_in[4];
    const float* outp_b = (const float*)d_in[5];
    const float* inproj = (const float*)d_in[6];
    const float* conv_w = (const float*)d_in[7];
    const float* conv_b = (const float*)d_in[8];
    const float* xproj  = (const float*)d_in[9];
    const float* dtw    = (const float*)d_in[10];
    const float* dtb    = (const float*)d_in[11];
    const float* A_log  = (const float*)d_in[12];
    const float* Dp     = (const float*)d_in[13];
    const float* mow    = (const float*)d_in[14];
    float* out = (float*)d_out;

    __nv_bfloat16 *wtH, *wtL, *wcH, *wcL, *xnH, *xnL, *yH, *yL;
    float *xz;
    cudaGetSymbolAddress((void**)&wtH, g_WtH);
    cudaGetSymbolAddress((void**)&wtL, g_WtL);
    cudaGetSymbolAddress((void**)&wcH, g_WcH);
    cudaGetSymbolAddress((void**)&wcL, g_WcL);
    cudaGetSymbolAddress((void**)&xnH, g_XnH);
    cudaGetSymbolAddress((void**)&xnL, g_XnL);
    cudaGetSymbolAddress((void**)&yH, g_yH);
    cudaGetSymbolAddress((void**)&yL, g_yL);
    cudaGetSymbolAddress((void**)&xz, g_xz);

    cudaFuncSetAttribute(k_mma<256, false>,
                         cudaFuncAttributeMaxDynamicSharedMemorySize, SMEM_MMA);
    cudaFuncSetAttribute(k_mma<512, true>,
                         cudaFuncAttributeMaxDynamicSharedMemorySize, SMEM_MMA);
    cudaFuncSetAttribute(k_scanC,
                         cudaFuncAttributeMaxDynamicSharedMemorySize, SMEM_SCANC);

    k_wt<<<dim3(32, 8), dim3(32, 8)>>>(inproj);
    k_wc<<<512, 128>>>(mow, outp_w);
    k_ln<<<256, 256>>>(input, input2, ln_g, ln_b);
    k_mma<256, false><<<dim3(128, 8), 256, SMEM_MMA>>>(wtH, wtL, xnH, xnL, xz, nullptr);
    k_conv<<<dim3(16, 512), 256>>>(conv_w, conv_b);
    k_xproj<<<256, 256>>>(xproj, dtw, dtb);
    k_scanA<<<dim3(32, 64), 256>>>(A_log);
    k_scanB<<<128, 256>>>();
    k_scanC<<<dim3(32, 64), 256, SMEM_SCANC>>>(A_log, Dp);
    k_mma<512, true><<<dim3(128, 1), 256, SMEM_MMA>>>(wcH, wcL, yH, yL, out, outp_b);
}